// round 2
// baseline (speedup 1.0000x reference)
#include <cuda_runtime.h>

// ---- problem constants ----
#define NROWS   8192      // N * OH * OW = 8*32*32
#define IDIM    72        // IC*KH*KW
#define OCH     16
#define NP      5
#define REC     28        // global param record stride (floats), 7x float4
#define RECS    29        // smem record stride (floats) -> conflict-free
#define RPB     16        // rows per block
#define CHUNK   8         // i-values per smem chunk
#define NCHUNK  9         // 72/8

// param record: [0]=l2 [1]=l [2..6]=z [7..11]=alpha [12..26]=W(lower,15) [27]=pad
__device__ float g_params[IDIM * OCH * REC];

// ---------------- precompute: per (o,i) GP neuron, fp64 ----------------
__global__ void gp_pre(const float* __restrict__ z,
                       const float* __restrict__ h,
                       const float* __restrict__ raw_l) {
    int pid = blockIdx.x * blockDim.x + threadIdx.x;
    if (pid >= IDIM * OCH) return;
    int o = pid / IDIM, i = pid - o * IDIM;
    int oi = o * IDIM + i;

    double x  = (double)raw_l[oi];
    double sp = log1p(exp(x));       // softplus
    double l2 = sp * sp;

    double zz[NP], hh[NP];
#pragma unroll
    for (int p = 0; p < NP; ++p) {
        zz[p] = (double)z[oi * NP + p];
        hh[p] = (double)h[oi * NP + p];
    }

    double Km[NP][NP];
#pragma unroll
    for (int p = 0; p < NP; ++p)
#pragma unroll
        for (int q = 0; q < NP; ++q) {
            double dz = zz[p] - zz[q];
            Km[p][q] = exp(-0.5 * dz * dz / l2) + (p == q ? 1e-4 : 0.0);
        }

    // Cholesky K = L L^T (SPD, no pivoting needed)
    double L[NP][NP];
#pragma unroll
    for (int j = 0; j < NP; ++j) {
        double s = Km[j][j];
#pragma unroll
        for (int k = 0; k < NP; ++k) if (k < j) s -= L[j][k] * L[j][k];
        double Ljj = sqrt(s);
        L[j][j] = Ljj;
#pragma unroll
        for (int r = 0; r < NP; ++r) if (r > j) {
            double t = Km[r][j];
#pragma unroll
            for (int k = 0; k < NP; ++k) if (k < j) t -= L[r][k] * L[j][k];
            L[r][j] = t / Ljj;
        }
    }
    // W = L^{-1} (lower): K^{-1} = W^T W
    double W[NP][NP];
#pragma unroll
    for (int j = 0; j < NP; ++j) {
        W[j][j] = 1.0 / L[j][j];
#pragma unroll
        for (int r = 0; r < NP; ++r) if (r > j) {
            double t = 0.0;
#pragma unroll
            for (int k = 0; k < NP; ++k) if (k >= j && k < r) t += L[r][k] * W[k][j];
            W[r][j] = -t / L[r][r];
        }
    }
    // alpha = K^{-1} h = W^T (W h)
    double tv[NP], al[NP];
#pragma unroll
    for (int p = 0; p < NP; ++p) {
        double s = 0.0;
#pragma unroll
        for (int q = 0; q < NP; ++q) if (q <= p) s += W[p][q] * hh[q];
        tv[p] = s;
    }
#pragma unroll
    for (int q = 0; q < NP; ++q) {
        double s = 0.0;
#pragma unroll
        for (int p = 0; p < NP; ++p) if (p >= q) s += W[p][q] * tv[p];
        al[q] = s;
    }

    float* rec = g_params + (i * OCH + o) * REC;   // i-major for chunked staging
    rec[0] = (float)l2;
    rec[1] = (float)sp;
#pragma unroll
    for (int p = 0; p < NP; ++p) rec[2 + p] = (float)zz[p];
#pragma unroll
    for (int p = 0; p < NP; ++p) rec[7 + p] = (float)al[p];
#pragma unroll
    for (int p = 0; p < NP; ++p)
#pragma unroll
        for (int q = 0; q < NP; ++q) if (q <= p)
            rec[12 + p * (p + 1) / 2 + q] = (float)W[p][q];
    rec[27] = 0.0f;
}

// ---------------- fast exp on FMA pipe (no MUFU) ----------------
__device__ __forceinline__ float fexp(float a) {           // a <= 0
    float y = a * 1.442695040888963f;
    y = fmaxf(y, -126.0f);
    float zf = y + 12582912.0f;                 // 1.5*2^23: round-to-nearest
    int   n  = __float_as_int(zf) - 0x4B400000; // n = round(y)
    float f  = y - (zf - 12582912.0f);          // f in [-0.5, 0.5]
    float p = 1.33335581464284e-3f;             // 2^f Taylor deg-5
    p = fmaf(p, f, 9.61812910762848e-3f);
    p = fmaf(p, f, 5.55041086648216e-2f);
    p = fmaf(p, f, 2.40226506959101e-1f);
    p = fmaf(p, f, 6.93147180559945e-1f);
    p = fmaf(p, f, 1.0f);
    float sc = __int_as_float((n << 23) + 0x3F800000);
    return p * sc;
}

// ---------------- main: rows x (o-groups) ----------------
__global__ __launch_bounds__(128) void gp_main(const float* __restrict__ xm,
                                               const float* __restrict__ xv,
                                               float* __restrict__ out) {
    __shared__ float mu_sm[RPB][IDIM + 1];     // stride 73 -> conflict-free
    __shared__ float s2_sm[RPB][IDIM + 1];
    __shared__ float prm_sm[CHUNK * OCH * RECS];

    const int tid  = threadIdx.x;
    const int row0 = blockIdx.x * RPB;

    // stage im2col(mu), im2col(s2) for this CTA's rows
    for (int idx = tid; idx < RPB * IDIM; idx += 128) {
        int rl = idx / IDIM, i = idx - rl * IDIM;
        int c = i / 9, rem = i - c * 9;
        int kh = rem / 3, kw = rem - kh * 3;
        int r = row0 + rl;
        int n = r >> 10, oh = (r >> 5) & 31, ow = r & 31;
        int ih = oh + kh - 1, iw = ow + kw - 1;
        float m = 0.0f, v = 0.0f;
        if ((unsigned)ih < 32u && (unsigned)iw < 32u) {
            int g = ((n * 32 + ih) * 32 + iw) * 8 + c;
            m = xm[g]; v = xv[g];
        }
        mu_sm[rl][i] = m;
        s2_sm[rl][i] = v;
    }

    const int og = tid & 7;          // 8 o-groups of 2
    const int rl = tid >> 3;         // 16 rows
    float macc[2] = {0.0f, 0.0f};
    float qacc[2] = {0.0f, 0.0f};

    for (int chunk = 0; chunk < NCHUNK; ++chunk) {
        __syncthreads();
        {   // stage param chunk: 8 i x 16 o x 28 floats (coalesced float4)
            const float4* src = reinterpret_cast<const float4*>(
                g_params + chunk * CHUNK * OCH * REC);
            for (int idx = tid; idx < CHUNK * OCH * (REC / 4); idx += 128) {
                float4 v4 = src[idx];
                int rrec = idx / 7, k4 = (idx - rrec * 7) * 4;
                float* dst = &prm_sm[rrec * RECS + k4];
                dst[0] = v4.x; dst[1] = v4.y; dst[2] = v4.z; dst[3] = v4.w;
            }
        }
        __syncthreads();

        for (int ii = 0; ii < CHUNK; ++ii) {
            const int i = chunk * CHUNK + ii;
            const float mu = mu_sm[rl][i];
            const float s2 = s2_sm[rl][i];
#pragma unroll
            for (int oo = 0; oo < 2; ++oo) {
                const float* Pr = &prm_sm[(ii * OCH + (og * 2 + oo)) * RECS];
                const float l2 = Pr[0], l = Pr[1];
                const float d = l2 + s2;
                // fast rsqrt: bit hack + 2 Newton (d in [0.48, 2.8])
                float r = __uint_as_float(0x5F3759DFu - (__float_as_uint(d) >> 1));
                const float hr = 0.5f * d;
                r = r * fmaf(-(hr * r), r, 1.5f);
                r = r * fmaf(-(hr * r), r, 1.5f);
                const float cc = -0.5f * (r * r);   // = -1/(2d)
                const float s  = l * r;             // = sqrt(l2/d)

                float e0, e1, e2, e3, e4;
                { float t = mu - Pr[2]; e0 = fexp((t * t) * cc); }
                { float t = mu - Pr[3]; e1 = fexp((t * t) * cc); }
                { float t = mu - Pr[4]; e2 = fexp((t * t) * cc); }
                { float t = mu - Pr[5]; e3 = fexp((t * t) * cc); }
                { float t = mu - Pr[6]; e4 = fexp((t * t) * cc); }

                // mean: e . alpha
                float me = e0 * Pr[7];
                me = fmaf(e1, Pr[8],  me);
                me = fmaf(e2, Pr[9],  me);
                me = fmaf(e3, Pr[10], me);
                me = fmaf(e4, Pr[11], me);

                // qKq = || W e ||^2  (W lower-tri, 15 entries)
                const float* Wp = Pr + 12;
                float v0 = Wp[0] * e0;
                float v1 = fmaf(Wp[2],  e1, Wp[1] * e0);
                float v2 = fmaf(Wp[5],  e2, fmaf(Wp[4],  e1, Wp[3] * e0));
                float v3 = fmaf(Wp[9],  e3, fmaf(Wp[8],  e2, fmaf(Wp[7],  e1, Wp[6]  * e0)));
                float v4 = fmaf(Wp[14], e4, fmaf(Wp[13], e3, fmaf(Wp[12], e2,
                           fmaf(Wp[11], e1, Wp[10] * e0))));
                float qkq = fmaf(v4, v4, fmaf(v3, v3, fmaf(v2, v2, fmaf(v1, v1, v0 * v0))));

                macc[oo] = fmaf(s, me, macc[oo]);
                qacc[oo] = fmaf(s * s, qkq, qacc[oo]);
            }
        }
    }

    const int r = row0 + rl;
#pragma unroll
    for (int oo = 0; oo < 2; ++oo) {
        const int o = og * 2 + oo;
        out[r * OCH + o] = macc[oo];
        out[NROWS * OCH + r * OCH + o] = fmaxf(72.0f - qacc[oo], 1e-6f);
    }
}

extern "C" void kernel_launch(void* const* d_in, const int* in_sizes, int n_in,
                              void* d_out, int out_size) {
    const float* xm  = (const float*)d_in[0];  // x_mean [8,32,32,8]
    const float* xv  = (const float*)d_in[1];  // x_var
    const float* z   = (const float*)d_in[2];  // [16,72,5]
    const float* h   = (const float*)d_in[3];  // [16,72,5]
    const float* rlp = (const float*)d_in[4];  // [16,72]
    float* out = (float*)d_out;                // [m (131072) | v (131072)]

    gp_pre<<<(IDIM * OCH + 127) / 128, 128>>>(z, h, rlp);
    gp_main<<<NROWS / RPB, 128>>>(xm, xv, out);
}

// round 3
// speedup vs baseline: 1.2210x; 1.2210x over previous
#include <cuda_runtime.h>

// ---- problem constants ----
#define NROWS   8192      // N * OH * OW = 8*32*32
#define IDIM    72        // IC*KH*KW
#define OCH     16
#define NP      5
#define RK      32        // float2 entries per record (l2,l,z*5,z2*5,alpha*5,W*15)
#define RECF    64        // floats per record in global (= RK*2, exactly, no pad)
#define RECS    68        // smem float stride per record -> og*68%32 = {0,4,...,28} conflict-free
#define RPB     16        // rows per block
#define CHUNK   12        // i-values per smem chunk
#define NCHUNK  6         // 72/12

// global param table: [i][og][RECF] floats, og = o>>1, float2-interleaved over lane=o&1
__device__ float g_params[IDIM * 8 * RECF];

typedef unsigned long long u64;

// ---------------- packed f32x2 helpers ----------------
__device__ __forceinline__ u64 pk2(unsigned lo, unsigned hi) {
    u64 d; asm("mov.b64 %0,{%1,%2};" : "=l"(d) : "r"(lo), "r"(hi)); return d;
}
__device__ __forceinline__ void upk(u64 v, unsigned& lo, unsigned& hi) {
    asm("mov.b64 {%0,%1},%2;" : "=r"(lo), "=r"(hi) : "l"(v));
}
__device__ __forceinline__ u64 bc(float f) {
    unsigned u = __float_as_uint(f); return pk2(u, u);
}
__device__ __forceinline__ u64 f2fma(u64 a, u64 b, u64 c) {
    u64 d; asm("fma.rn.f32x2 %0,%1,%2,%3;" : "=l"(d) : "l"(a), "l"(b), "l"(c)); return d;
}
__device__ __forceinline__ u64 f2mul(u64 a, u64 b) {
    u64 d; asm("mul.rn.f32x2 %0,%1,%2;" : "=l"(d) : "l"(a), "l"(b)); return d;
}
__device__ __forceinline__ u64 f2add(u64 a, u64 b) {
    u64 d; asm("add.rn.f32x2 %0,%1,%2;" : "=l"(d) : "l"(a), "l"(b)); return d;
}

// ---------------- precompute: per (o,i) GP neuron, fp64, spread wide ----------------
__global__ void gp_pre(const float* __restrict__ z,
                       const float* __restrict__ h,
                       const float* __restrict__ raw_l) {
    int pid = blockIdx.x * blockDim.x + threadIdx.x;
    if (pid >= IDIM * OCH) return;
    int o = pid / IDIM, i = pid - o * IDIM;
    int oi = o * IDIM + i;

    double x  = (double)raw_l[oi];
    double sp = log1p(exp(x));       // softplus
    double l2 = sp * sp;

    double zz[NP], hh[NP];
#pragma unroll
    for (int p = 0; p < NP; ++p) {
        zz[p] = (double)z[oi * NP + p];
        hh[p] = (double)h[oi * NP + p];
    }

    double Km[NP][NP];
#pragma unroll
    for (int p = 0; p < NP; ++p)
#pragma unroll
        for (int q = 0; q < NP; ++q) {
            double dz = zz[p] - zz[q];
            Km[p][q] = exp(-0.5 * dz * dz / l2) + (p == q ? 1e-4 : 0.0);
        }

    // Cholesky K = L L^T
    double L[NP][NP];
#pragma unroll
    for (int j = 0; j < NP; ++j) {
        double s = Km[j][j];
#pragma unroll
        for (int k = 0; k < NP; ++k) if (k < j) s -= L[j][k] * L[j][k];
        double Ljj = sqrt(s);
        L[j][j] = Ljj;
#pragma unroll
        for (int r = 0; r < NP; ++r) if (r > j) {
            double t = Km[r][j];
#pragma unroll
            for (int k = 0; k < NP; ++k) if (k < j) t -= L[r][k] * L[j][k];
            L[r][j] = t / Ljj;
        }
    }
    // W = L^{-1} (lower): K^{-1} = W^T W
    double W[NP][NP];
#pragma unroll
    for (int j = 0; j < NP; ++j) {
        W[j][j] = 1.0 / L[j][j];
#pragma unroll
        for (int r = 0; r < NP; ++r) if (r > j) {
            double t = 0.0;
#pragma unroll
            for (int k = 0; k < NP; ++k) if (k >= j && k < r) t += L[r][k] * W[k][j];
            W[r][j] = -t / L[r][r];
        }
    }
    // alpha = K^{-1} h = W^T (W h)
    double tv[NP], al[NP];
#pragma unroll
    for (int p = 0; p < NP; ++p) {
        double s = 0.0;
#pragma unroll
        for (int q = 0; q < NP; ++q) if (q <= p) s += W[p][q] * hh[q];
        tv[p] = s;
    }
#pragma unroll
    for (int q = 0; q < NP; ++q) {
        double s = 0.0;
#pragma unroll
        for (int p = 0; p < NP; ++p) if (p >= q) s += W[p][q] * tv[p];
        al[q] = s;
    }

    // interleaved store: record (i, og), lane = o&1, float2 entry k
    int og = o >> 1, lane = o & 1;
    float* rec = g_params + (i * 8 + og) * RECF + lane;
    rec[0 * 2]  = (float)l2;
    rec[1 * 2]  = (float)sp;
#pragma unroll
    for (int p = 0; p < NP; ++p) rec[(2 + p) * 2]  = (float)zz[p];
#pragma unroll
    for (int p = 0; p < NP; ++p) rec[(7 + p) * 2]  = (float)(zz[p] * zz[p]);
#pragma unroll
    for (int p = 0; p < NP; ++p) rec[(12 + p) * 2] = (float)al[p];
#pragma unroll
    for (int p = 0; p < NP; ++p)
#pragma unroll
        for (int q = 0; q < NP; ++q) if (q <= p)
            rec[(17 + p * (p + 1) / 2 + q) * 2] = (float)W[p][q];
}

// ---------------- main: rows x o-pairs, packed f32x2 everywhere ----------------
__global__ __launch_bounds__(128) void gp_main(const float* __restrict__ xm,
                                               const float* __restrict__ xv,
                                               float* __restrict__ out) {
    __shared__ __align__(16) float mu_sm[RPB][IDIM + 1];   // stride 73 -> conflict-free
    __shared__ __align__(16) float s2_sm[RPB][IDIM + 1];
    __shared__ __align__(16) float prm[CHUNK * 8 * RECS];

    const int tid  = threadIdx.x;
    const int row0 = blockIdx.x * RPB;

    // stage im2col(mu), im2col(s2) for this CTA's rows
    for (int idx = tid; idx < RPB * IDIM; idx += 128) {
        int rl = idx / IDIM, i = idx - rl * IDIM;
        int c = i / 9, rem = i - c * 9;
        int kh = rem / 3, kw = rem - kh * 3;
        int r = row0 + rl;
        int n = r >> 10, oh = (r >> 5) & 31, ow = r & 31;
        int ih = oh + kh - 1, iw = ow + kw - 1;
        float m = 0.0f, v = 0.0f;
        if ((unsigned)ih < 32u && (unsigned)iw < 32u) {
            int g = ((n * 32 + ih) * 32 + iw) * 8 + c;
            m = xm[g]; v = xv[g];
        }
        mu_sm[rl][i] = m;
        s2_sm[rl][i] = v;
    }

    const int og = tid & 7;          // 8 o-pairs
    const int rl = tid >> 3;         // 16 rows

    // packed constants (hoisted into registers once)
    const u64 C_NHALF  = bc(-0.5f);
    const u64 C_1P5    = bc(1.5f);
    const u64 C_N1     = bc(-1.0f);
    const u64 C_MAGIC  = bc(12582912.0f);
    const u64 C_NMAGIC = bc(-12582912.0f);
    const u64 C_NHL2E  = bc(-0.7213475204444817f);   // -0.5*log2(e)
    const u64 C_P5 = bc(1.33335581464284e-3f);
    const u64 C_P4 = bc(9.61812910762848e-3f);
    const u64 C_P3 = bc(5.55041086648216e-2f);
    const u64 C_P2 = bc(2.40226506959101e-1f);
    const u64 C_P1 = bc(6.93147180559945e-1f);
    const u64 C_ONE = bc(1.0f);

    u64 macc = 0ULL;     // packed (0.0f, 0.0f)
    u64 qacc = 0ULL;

    for (int chunk = 0; chunk < NCHUNK; ++chunk) {
        __syncthreads();
        {   // stage param chunk: CHUNK i x 8 og x 16 uint4 records (coalesced)
            const uint4* src = reinterpret_cast<const uint4*>(
                g_params + chunk * CHUNK * 8 * RECF);
            for (int idx = tid; idx < CHUNK * 8 * 16; idx += 128) {
                int rrec = idx >> 4, k4 = idx & 15;
                uint4 v4 = src[idx];
                *reinterpret_cast<uint4*>(&prm[rrec * RECS + 4 * k4]) = v4;
            }
        }
        __syncthreads();

        for (int ii = 0; ii < CHUNK; ++ii) {
            const int i = chunk * CHUNK + ii;
            const float mu  = mu_sm[rl][i];
            const float s2v = s2_sm[rl][i];
            const u64 MUSQ = bc(mu * mu);
            const u64 NM2  = bc(-2.0f * mu);
            const u64 S2   = bc(s2v);

            // load record: 16x LDS.128, 8 og's hit distinct bank groups, 4 lanes broadcast
            const uint4* Rq = reinterpret_cast<const uint4*>(&prm[(ii * 8 + og) * RECS]);
            u64 P[RK];
#pragma unroll
            for (int k4 = 0; k4 < 16; ++k4) {
                uint4 q = Rq[k4];
                P[2 * k4]     = pk2(q.x, q.y);
                P[2 * k4 + 1] = pk2(q.z, q.w);
            }
            const u64 l2 = P[0], l = P[1];

            // d = l2 + s2; packed fast rsqrt (bit hack + 2 Newton)
            u64 d = f2add(l2, S2);
            unsigned dlo, dhi; upk(d, dlo, dhi);
            u64 r = pk2(0x5F3759DFu - (dlo >> 1), 0x5F3759DFu - (dhi >> 1));
            u64 nhr = f2mul(C_NHALF, d);
            u64 rr = f2mul(r, r); u64 w = f2fma(nhr, rr, C_1P5); r = f2mul(r, w);
            rr = f2mul(r, r);     w = f2fma(nhr, rr, C_1P5);     r = f2mul(r, w);
            rr = f2mul(r, r);                       // ~ 1/d
            const u64 ccp  = f2mul(rr, C_NHL2E);    // -log2e/(2d)
            const u64 ss   = f2mul(l2, rr);         // l2/d
            const u64 s    = f2mul(l, r);           // sqrt(l2/d)
            const u64 up   = f2mul(ccp, NM2);       // ccp * (-2 mu)
            const u64 base = f2mul(ccp, MUSQ);      // ccp * mu^2

            // 5 expected-kernel values: e_p = 2^(base + up*z_p + ccp*z_p^2)
            u64 e[NP];
#pragma unroll
            for (int p = 0; p < NP; ++p) {
                u64 y  = f2fma(up, P[2 + p], f2fma(ccp, P[7 + p], base));
                u64 zf = f2add(y, C_MAGIC);
                unsigned zlo, zhi; upk(zf, zlo, zhi);
                u64 sc = pk2((zlo << 23) + 0x3F800000u, (zhi << 23) + 0x3F800000u);
                u64 nf = f2add(zf, C_NMAGIC);
                u64 f  = f2fma(nf, C_N1, y);
                u64 pp = f2fma(C_P5, f, C_P4);
                pp = f2fma(pp, f, C_P3);
                pp = f2fma(pp, f, C_P2);
                pp = f2fma(pp, f, C_P1);
                pp = f2fma(pp, f, C_ONE);
                e[p] = f2mul(pp, sc);
            }

            // mean: e . alpha   (alpha at P[12..16])
            u64 me = f2mul(e[0], P[12]);
            me = f2fma(e[1], P[13], me);
            me = f2fma(e[2], P[14], me);
            me = f2fma(e[3], P[15], me);
            me = f2fma(e[4], P[16], me);

            // qKq = ||W e||^2  (W lower-tri at P[17..31])
            u64 v0 = f2mul(P[17], e[0]);
            u64 v1 = f2fma(P[19], e[1], f2mul(P[18], e[0]));
            u64 v2 = f2fma(P[22], e[2], f2fma(P[21], e[1], f2mul(P[20], e[0])));
            u64 v3 = f2fma(P[26], e[3], f2fma(P[25], e[2],
                     f2fma(P[24], e[1], f2mul(P[23], e[0]))));
            u64 v4 = f2fma(P[31], e[4], f2fma(P[30], e[3],
                     f2fma(P[29], e[2], f2fma(P[28], e[1], f2mul(P[27], e[0])))));
            u64 qk = f2mul(v0, v0);
            qk = f2fma(v1, v1, qk);
            qk = f2fma(v2, v2, qk);
            qk = f2fma(v3, v3, qk);
            qk = f2fma(v4, v4, qk);

            macc = f2fma(s,  me, macc);
            qacc = f2fma(ss, qk, qacc);
        }
    }

    const int r = row0 + rl;
    unsigned mlo, mhi, qlo, qhi;
    upk(macc, mlo, mhi); upk(qacc, qlo, qhi);
    float2 mo = make_float2(__uint_as_float(mlo), __uint_as_float(mhi));
    float2 vo = make_float2(fmaxf(72.0f - __uint_as_float(qlo), 1e-6f),
                            fmaxf(72.0f - __uint_as_float(qhi), 1e-6f));
    reinterpret_cast<float2*>(out)[r * 8 + og] = mo;
    reinterpret_cast<float2*>(out + NROWS * OCH)[r * 8 + og] = vo;
}

extern "C" void kernel_launch(void* const* d_in, const int* in_sizes, int n_in,
                              void* d_out, int out_size) {
    const float* xm  = (const float*)d_in[0];  // x_mean [8,32,32,8]
    const float* xv  = (const float*)d_in[1];  // x_var
    const float* z   = (const float*)d_in[2];  // [16,72,5]
    const float* h   = (const float*)d_in[3];  // [16,72,5]
    const float* rlp = (const float*)d_in[4];  // [16,72]
    float* out = (float*)d_out;                // [m (131072) | v (131072)]

    gp_pre<<<72, 16>>>(z, h, rlp);             // 1152 tasks spread over 72 SMs
    gp_main<<<NROWS / RPB, 128>>>(xm, xv, out);
}

// round 4
// speedup vs baseline: 1.6219x; 1.3283x over previous
#include <cuda_runtime.h>

// ---- problem constants ----
#define NROWS   8192      // N * OH * OW = 8*32*32
#define IDIM    72        // IC*KH*KW
#define OCH     16
#define NP      5
#define RKU     28        // u64 entries per record: l2,l,negz*5,alpha*5,W*15,pad
#define RECF    56        // floats per record in global (= RKU*2)
#define RECS    60        // smem float stride: og*60%32 = {0,28,24,20,16,12,8,4} conflict-free
#define ROWSB   32        // rows per CTA
#define RPT     2         // rows per thread
#define CHUNK   12        // i-values per smem chunk
#define NCHUNK  6         // 72/12

// global param table: [i][og][RECF] floats, og = o>>1, float2-interleaved over lane=o&1
__device__ float g_params[IDIM * 8 * RECF];

typedef unsigned long long u64;

// ---------------- packed f32x2 helpers ----------------
__device__ __forceinline__ u64 pk2(unsigned lo, unsigned hi) {
    u64 d; asm("mov.b64 %0,{%1,%2};" : "=l"(d) : "r"(lo), "r"(hi)); return d;
}
__device__ __forceinline__ void upk(u64 v, unsigned& lo, unsigned& hi) {
    asm("mov.b64 {%0,%1},%2;" : "=r"(lo), "=r"(hi) : "l"(v));
}
__device__ __forceinline__ u64 bc(float f) {
    unsigned u = __float_as_uint(f); return pk2(u, u);
}
__device__ __forceinline__ u64 f2fma(u64 a, u64 b, u64 c) {
    u64 d; asm("fma.rn.f32x2 %0,%1,%2,%3;" : "=l"(d) : "l"(a), "l"(b), "l"(c)); return d;
}
__device__ __forceinline__ u64 f2mul(u64 a, u64 b) {
    u64 d; asm("mul.rn.f32x2 %0,%1,%2;" : "=l"(d) : "l"(a), "l"(b)); return d;
}
__device__ __forceinline__ u64 f2add(u64 a, u64 b) {
    u64 d; asm("add.rn.f32x2 %0,%1,%2;" : "=l"(d) : "l"(a), "l"(b)); return d;
}

// ---------------- precompute: hybrid fp32-exp / fp64-solve ----------------
__global__ void gp_pre(const float* __restrict__ z,
                       const float* __restrict__ h,
                       const float* __restrict__ raw_l) {
    int pid = blockIdx.x * blockDim.x + threadIdx.x;
    if (pid >= IDIM * OCH) return;
    int o = pid / IDIM, i = pid - o * IDIM;
    int oi = o * IDIM + i;

    double x  = (double)raw_l[oi];
    double sp = log1p(exp(x));       // softplus (1 fp64 exp, cheap)
    double l2 = sp * sp;
    float  l2f = (float)l2;

    float zzf[NP]; double hh[NP];
#pragma unroll
    for (int p = 0; p < NP; ++p) {
        zzf[p] = z[oi * NP + p];
        hh[p]  = (double)h[oi * NP + p];
    }

    // K entries in fp32 (matches the reference's own fp32 K formation)
    double Km[NP][NP];
#pragma unroll
    for (int p = 0; p < NP; ++p)
#pragma unroll
        for (int q = 0; q < NP; ++q) {
            float dz = zzf[p] - zzf[q];
            Km[p][q] = (double)expf(-0.5f * dz * dz / l2f) + (p == q ? 1e-4 : 0.0);
        }

    // Cholesky K = L L^T (fp64, ~no transcendentals)
    double L[NP][NP];
#pragma unroll
    for (int j = 0; j < NP; ++j) {
        double s = Km[j][j];
#pragma unroll
        for (int k = 0; k < NP; ++k) if (k < j) s -= L[j][k] * L[j][k];
        double Ljj = sqrt(s);
        L[j][j] = Ljj;
#pragma unroll
        for (int r = 0; r < NP; ++r) if (r > j) {
            double t = Km[r][j];
#pragma unroll
            for (int k = 0; k < NP; ++k) if (k < j) t -= L[r][k] * L[j][k];
            L[r][j] = t / Ljj;
        }
    }
    // W = L^{-1} (lower): K^{-1} = W^T W
    double W[NP][NP];
#pragma unroll
    for (int j = 0; j < NP; ++j) {
        W[j][j] = 1.0 / L[j][j];
#pragma unroll
        for (int r = 0; r < NP; ++r) if (r > j) {
            double t = 0.0;
#pragma unroll
            for (int k = 0; k < NP; ++k) if (k >= j && k < r) t += L[r][k] * W[k][j];
            W[r][j] = -t / L[r][r];
        }
    }
    // alpha = K^{-1} h = W^T (W h)
    double tv[NP], al[NP];
#pragma unroll
    for (int p = 0; p < NP; ++p) {
        double s = 0.0;
#pragma unroll
        for (int q = 0; q < NP; ++q) if (q <= p) s += W[p][q] * hh[q];
        tv[p] = s;
    }
#pragma unroll
    for (int q = 0; q < NP; ++q) {
        double s = 0.0;
#pragma unroll
        for (int p = 0; p < NP; ++p) if (p >= q) s += W[p][q] * tv[p];
        al[q] = s;
    }

    // interleaved store: record (i, og), lane = o&1, float2 entry k
    int og = o >> 1, lane = o & 1;
    float* rec = g_params + (i * 8 + og) * RECF + lane;
    rec[0 * 2] = (float)l2;
    rec[1 * 2] = (float)sp;
#pragma unroll
    for (int p = 0; p < NP; ++p) rec[(2 + p) * 2] = -zzf[p];          // NEGATED z
#pragma unroll
    for (int p = 0; p < NP; ++p) rec[(7 + p) * 2] = (float)al[p];
#pragma unroll
    for (int p = 0; p < NP; ++p)
#pragma unroll
        for (int q = 0; q < NP; ++q) if (q <= p)
            rec[(12 + p * (p + 1) / 2 + q) * 2] = (float)W[p][q];
    rec[27 * 2] = 0.0f;
}

// ---------------- main: 2 rows/thread, record held in registers ----------------
__global__ __launch_bounds__(128) void gp_main(const float* __restrict__ xm,
                                               const float* __restrict__ xv,
                                               float* __restrict__ out) {
    __shared__ __align__(16) float2 ms_sm[IDIM][ROWSB + 1];   // (mu, s2)
    __shared__ __align__(16) float  prm[CHUNK * 8 * RECS];

    const int tid  = threadIdx.x;
    const int row0 = blockIdx.x * ROWSB;

    // stage im2col(mu,s2) as float2 [i][row]
    for (int idx = tid; idx < IDIM * ROWSB; idx += 128) {
        int i = idx >> 5, rlocal = idx & 31;
        int c = i / 9, rem = i - c * 9;
        int kh = rem / 3, kw = rem - kh * 3;
        int r = row0 + rlocal;
        int n = r >> 10, oh = (r >> 5) & 31, ow = r & 31;
        int ih = oh + kh - 1, iw = ow + kw - 1;
        float m = 0.0f, v = 0.0f;
        if ((unsigned)ih < 32u && (unsigned)iw < 32u) {
            int g = ((n * 32 + ih) * 32 + iw) * 8 + c;
            m = xm[g]; v = xv[g];
        }
        ms_sm[i][rlocal] = make_float2(m, v);
    }

    const int og = tid & 7;          // 8 o-pairs
    const int rp = tid >> 3;         // 16 row-pairs -> rows rp*2, rp*2+1

    // packed constants
    const u64 C_NHALF  = bc(-0.5f);
    const u64 C_1P5    = bc(1.5f);
    const u64 C_N1     = bc(-1.0f);
    const u64 C_MAGIC  = bc(12582912.0f);
    const u64 C_NMAGIC = bc(-12582912.0f);
    const u64 C_NHL2E  = bc(-0.7213475204444817f);   // -0.5*log2(e)
    const u64 C_P5 = bc(1.33335581464284e-3f);
    const u64 C_P4 = bc(9.61812910762848e-3f);
    const u64 C_P3 = bc(5.55041086648216e-2f);
    const u64 C_P2 = bc(2.40226506959101e-1f);
    const u64 C_P1 = bc(6.93147180559945e-1f);
    const u64 C_ONE = bc(1.0f);

    u64 macc[RPT] = {0ULL, 0ULL};
    u64 qacc[RPT] = {0ULL, 0ULL};

    for (int chunk = 0; chunk < NCHUNK; ++chunk) {
        __syncthreads();
        {   // stage param chunk: CHUNK i x 8 og x 14 uint4 records (coalesced)
            const uint4* src = reinterpret_cast<const uint4*>(
                g_params + chunk * CHUNK * 8 * RECF);
            for (int idx = tid; idx < CHUNK * 8 * 14; idx += 128) {
                int rrec = idx / 14, k4 = idx - rrec * 14;
                uint4 v4 = src[idx];
                *reinterpret_cast<uint4*>(&prm[rrec * RECS + 4 * k4]) = v4;
            }
        }
        __syncthreads();

        for (int ii = 0; ii < CHUNK; ++ii) {
            const int i = chunk * CHUNK + ii;

            // record -> registers once, reused for RPT rows
            const uint4* Rq = reinterpret_cast<const uint4*>(&prm[(ii * 8 + og) * RECS]);
            u64 P[RKU];
#pragma unroll
            for (int k4 = 0; k4 < 14; ++k4) {
                uint4 q = Rq[k4];
                P[2 * k4]     = pk2(q.x, q.y);
                P[2 * k4 + 1] = pk2(q.z, q.w);
            }
            const u64 l2 = P[0], l = P[1];

#pragma unroll
            for (int rr = 0; rr < RPT; ++rr) {
                const float2 msv = ms_sm[i][rp * 2 + rr];
                const u64 MU = bc(msv.x);
                const u64 S2 = bc(msv.y);

                // d = l2 + s2; packed fast rsqrt (bit hack + 2 Newton)
                u64 d = f2add(l2, S2);
                unsigned dlo, dhi; upk(d, dlo, dhi);
                u64 r = pk2(0x5F3759DFu - (dlo >> 1), 0x5F3759DFu - (dhi >> 1));
                u64 nhr = f2mul(C_NHALF, d);
                u64 rsq = f2mul(r, r);
                u64 w = f2fma(nhr, rsq, C_1P5); r = f2mul(r, w);
                rsq = f2mul(r, r);
                w = f2fma(nhr, rsq, C_1P5);     r = f2mul(r, w);
                rsq = f2mul(r, r);                       // ~ 1/d
                const u64 ccp = f2mul(rsq, C_NHL2E);     // -log2e/(2d)
                const u64 ss  = f2mul(l2, rsq);          // l2/d
                const u64 s   = f2mul(l, r);             // sqrt(l2/d)

                // 5 expected-kernel values: e_p = 2^( ccp * (mu - z_p)^2 )
                u64 e[NP];
#pragma unroll
                for (int p = 0; p < NP; ++p) {
                    u64 t  = f2add(MU, P[2 + p]);        // P holds -z
                    u64 t2 = f2mul(t, t);
                    u64 y  = f2mul(t2, ccp);
                    u64 zf = f2add(y, C_MAGIC);
                    unsigned zlo, zhi; upk(zf, zlo, zhi);
                    u64 sc = pk2((zlo << 23) + 0x3F800000u, (zhi << 23) + 0x3F800000u);
                    u64 nf = f2add(zf, C_NMAGIC);
                    u64 f  = f2fma(nf, C_N1, y);
                    u64 pp = f2fma(C_P5, f, C_P4);
                    pp = f2fma(pp, f, C_P3);
                    pp = f2fma(pp, f, C_P2);
                    pp = f2fma(pp, f, C_P1);
                    pp = f2fma(pp, f, C_ONE);
                    e[p] = f2mul(pp, sc);
                }

                // mean: e . alpha  (alpha at P[7..11])
                u64 me = f2mul(e[0], P[7]);
                me = f2fma(e[1], P[8],  me);
                me = f2fma(e[2], P[9],  me);
                me = f2fma(e[3], P[10], me);
                me = f2fma(e[4], P[11], me);

                // qKq = ||W e||^2  (W lower-tri at P[12..26])
                u64 v0 = f2mul(P[12], e[0]);
                u64 v1 = f2fma(P[14], e[1], f2mul(P[13], e[0]));
                u64 v2 = f2fma(P[17], e[2], f2fma(P[16], e[1], f2mul(P[15], e[0])));
                u64 v3 = f2fma(P[21], e[3], f2fma(P[20], e[2],
                         f2fma(P[19], e[1], f2mul(P[18], e[0]))));
                u64 v4 = f2fma(P[26], e[4], f2fma(P[25], e[3],
                         f2fma(P[24], e[2], f2fma(P[23], e[1], f2mul(P[22], e[0])))));
                u64 qk = f2mul(v0, v0);
                qk = f2fma(v1, v1, qk);
                qk = f2fma(v2, v2, qk);
                qk = f2fma(v3, v3, qk);
                qk = f2fma(v4, v4, qk);

                macc[rr] = f2fma(s,  me, macc[rr]);
                qacc[rr] = f2fma(ss, qk, qacc[rr]);
            }
        }
    }

#pragma unroll
    for (int rr = 0; rr < RPT; ++rr) {
        const int r = row0 + rp * 2 + rr;
        unsigned mlo, mhi, qlo, qhi;
        upk(macc[rr], mlo, mhi); upk(qacc[rr], qlo, qhi);
        float2 mo = make_float2(__uint_as_float(mlo), __uint_as_float(mhi));
        float2 vo = make_float2(fmaxf(72.0f - __uint_as_float(qlo), 1e-6f),
                                fmaxf(72.0f - __uint_as_float(qhi), 1e-6f));
        reinterpret_cast<float2*>(out)[r * 8 + og] = mo;
        reinterpret_cast<float2*>(out + NROWS * OCH)[r * 8 + og] = vo;
    }
}

extern "C" void kernel_launch(void* const* d_in, const int* in_sizes, int n_in,
                              void* d_out, int out_size) {
    const float* xm  = (const float*)d_in[0];  // x_mean [8,32,32,8]
    const float* xv  = (const float*)d_in[1];  // x_var
    const float* z   = (const float*)d_in[2];  // [16,72,5]
    const float* h   = (const float*)d_in[3];  // [16,72,5]
    const float* rlp = (const float*)d_in[4];  // [16,72]
    float* out = (float*)d_out;                // [m (131072) | v (131072)]

    gp_pre<<<36, 32>>>(z, h, rlp);             // full warps, 36 SMs
    gp_main<<<NROWS / ROWSB, 128>>>(xm, xv, out);
}

// round 5
// speedup vs baseline: 1.9834x; 1.2229x over previous
#include <cuda_runtime.h>

// ---- problem constants ----
#define NROWS   8192      // N * OH * OW = 8*32*32
#define IDIM    72        // IC*KH*KW
#define OCH     16
#define NP      5
#define RKU     26        // u64 entries per record: l2, negz*5, alpha'*5, W'*15
#define RECF    52        // floats per record in global (= RKU*2) = 13 uint4
#define RECS    60        // smem float stride: og*60%32 distinct -> conflict-free
#define ROWSB   32        // rows per CTA
#define RPT     2         // rows per thread
#define ISPLIT  2
#define IHALF   36        // IDIM / ISPLIT
#define CHUNK   12        // i-values per smem chunk
#define NCHUNK  3         // 36/12

// global param table: [i][og][RECF] floats, og = o>>1, float2-interleaved over lane=o&1
__device__ float g_params[IDIM * 8 * RECF];
// partial sums: [split][row][og] -> float4(m.lo, m.hi, q.lo, q.hi)
__device__ float4 g_part[ISPLIT * NROWS * 8];

typedef unsigned long long u64;

// ---------------- packed f32x2 helpers ----------------
__device__ __forceinline__ u64 pk2(unsigned lo, unsigned hi) {
    u64 d; asm("mov.b64 %0,{%1,%2};" : "=l"(d) : "r"(lo), "r"(hi)); return d;
}
__device__ __forceinline__ void upk(u64 v, unsigned& lo, unsigned& hi) {
    asm("mov.b64 {%0,%1},%2;" : "=r"(lo), "=r"(hi) : "l"(v));
}
__device__ __forceinline__ u64 bc(float f) {
    unsigned u = __float_as_uint(f); return pk2(u, u);
}
__device__ __forceinline__ u64 f2fma(u64 a, u64 b, u64 c) {
    u64 d; asm("fma.rn.f32x2 %0,%1,%2,%3;" : "=l"(d) : "l"(a), "l"(b), "l"(c)); return d;
}
__device__ __forceinline__ u64 f2mul(u64 a, u64 b) {
    u64 d; asm("mul.rn.f32x2 %0,%1,%2;" : "=l"(d) : "l"(a), "l"(b)); return d;
}
__device__ __forceinline__ u64 f2add(u64 a, u64 b) {
    u64 d; asm("add.rn.f32x2 %0,%1,%2;" : "=l"(d) : "l"(a), "l"(b)); return d;
}

// ---------------- precompute: fp32 transcendentals, FMA-only fp64 solve ----------------
__global__ void gp_pre(const float* __restrict__ z,
                       const float* __restrict__ h,
                       const float* __restrict__ raw_l) {
    int pid = blockIdx.x * blockDim.x + threadIdx.x;
    if (pid >= IDIM * OCH) return;
    int o = pid / IDIM, i = pid - o * IDIM;
    int oi = o * IDIM + i;

    // softplus in fp32 (reference computes it in fp32 too)
    float x   = raw_l[oi];
    float spf = log1pf(expf(x));
    float l2f = spf * spf;
    double sp = (double)spf;

    float zzf[NP]; double hh[NP];
#pragma unroll
    for (int p = 0; p < NP; ++p) {
        zzf[p] = z[oi * NP + p];
        hh[p]  = (double)h[oi * NP + p];
    }

    // K entries in fp32 (matches reference), promoted to fp64 for the solve
    double Km[NP][NP];
#pragma unroll
    for (int p = 0; p < NP; ++p)
#pragma unroll
        for (int q = 0; q < NP; ++q) {
            float dz = zzf[p] - zzf[q];
            Km[p][q] = (double)expf(-0.5f * dz * dz / l2f) + (p == q ? 1e-4 : 0.0);
        }

    // Cholesky K = L L^T with rsqrt (no fp64 div/sqrt anywhere)
    double L[NP][NP];
    double rdiag[NP];          // 1/L[j][j]
#pragma unroll
    for (int j = 0; j < NP; ++j) {
        double s = Km[j][j];
#pragma unroll
        for (int k = 0; k < NP; ++k) if (k < j) s -= L[j][k] * L[j][k];
        double r = (double)rsqrtf((float)s);
        r = r * (1.5 - 0.5 * s * r * r);       // one fp64 Newton -> ~1e-14
        r = r * (1.5 - 0.5 * s * r * r);       // second for safety (cheap)
        rdiag[j] = r;
        L[j][j] = s * r;                        // sqrt(s)
#pragma unroll
        for (int rr = 0; rr < NP; ++rr) if (rr > j) {
            double t = Km[rr][j];
#pragma unroll
            for (int k = 0; k < NP; ++k) if (k < j) t -= L[rr][k] * L[j][k];
            L[rr][j] = t * r;
        }
    }
    // W = L^{-1} (lower): K^{-1} = W^T W
    double W[NP][NP];
#pragma unroll
    for (int j = 0; j < NP; ++j) {
        W[j][j] = rdiag[j];
#pragma unroll
        for (int rr = 0; rr < NP; ++rr) if (rr > j) {
            double t = 0.0;
#pragma unroll
            for (int k = 0; k < NP; ++k) if (k >= j && k < rr) t += L[rr][k] * W[k][j];
            W[rr][j] = -t * rdiag[rr];
        }
    }
    // alpha = K^{-1} h = W^T (W h)
    double tv[NP], al[NP];
#pragma unroll
    for (int p = 0; p < NP; ++p) {
        double s = 0.0;
#pragma unroll
        for (int q = 0; q < NP; ++q) if (q <= p) s += W[p][q] * hh[q];
        tv[p] = s;
    }
#pragma unroll
    for (int q = 0; q < NP; ++q) {
        double s = 0.0;
#pragma unroll
        for (int p = 0; p < NP; ++p) if (p >= q) s += W[p][q] * tv[p];
        al[q] = s;
    }

    // record (float2-interleaved): l2, -z*5, (l*alpha)*5, (l*W)*15
    int og = o >> 1, lane = o & 1;
    float* rec = g_params + (i * 8 + og) * RECF + lane;
    rec[0] = l2f;
#pragma unroll
    for (int p = 0; p < NP; ++p) rec[(1 + p) * 2]  = -zzf[p];
#pragma unroll
    for (int p = 0; p < NP; ++p) rec[(6 + p) * 2]  = (float)(sp * al[p]);
#pragma unroll
    for (int p = 0; p < NP; ++p)
#pragma unroll
        for (int q = 0; q < NP; ++q) if (q <= p)
            rec[(11 + p * (p + 1) / 2 + q) * 2] = (float)(sp * W[p][q]);
}

// ---------------- main: i-split halves, 2 rows/thread, records in registers ----------------
__global__ __launch_bounds__(128) void gp_main(const float* __restrict__ xm,
                                               const float* __restrict__ xv) {
    __shared__ __align__(16) float2 ms_sm[IHALF][ROWSB + 1];   // (mu, s2)
    __shared__ __align__(16) float  prm[CHUNK * 8 * RECS];

    const int tid   = threadIdx.x;
    const int row0  = blockIdx.x * ROWSB;
    const int split = blockIdx.y;
    const int i0    = split * IHALF;

    // stage im2col(mu,s2) for this CTA's rows, this split's i-range
    for (int idx = tid; idx < IHALF * ROWSB; idx += 128) {
        int il = idx >> 5, rlocal = idx & 31;
        int i = i0 + il;
        int c = i / 9, rem = i - c * 9;
        int kh = rem / 3, kw = rem - kh * 3;
        int r = row0 + rlocal;
        int n = r >> 10, oh = (r >> 5) & 31, ow = r & 31;
        int ih = oh + kh - 1, iw = ow + kw - 1;
        float m = 0.0f, v = 0.0f;
        if ((unsigned)ih < 32u && (unsigned)iw < 32u) {
            int g = ((n * 32 + ih) * 32 + iw) * 8 + c;
            m = xm[g]; v = xv[g];
        }
        ms_sm[il][rlocal] = make_float2(m, v);
    }

    const int og = tid & 7;          // 8 o-pairs
    const int rp = tid >> 3;         // 16 row-pairs -> rows rp*2, rp*2+1

    // packed constants
    const u64 C_N1     = bc(-1.0f);
    const u64 C_MAGIC  = bc(12582912.0f);
    const u64 C_NMAGIC = bc(-12582912.0f);
    const u64 C_NHL2E  = bc(-0.7213475204444817f);   // -0.5*log2(e)
    const u64 C_P5 = bc(1.33335581464284e-3f);
    const u64 C_P4 = bc(9.61812910762848e-3f);
    const u64 C_P3 = bc(5.55041086648216e-2f);
    const u64 C_P2 = bc(2.40226506959101e-1f);
    const u64 C_P1 = bc(6.93147180559945e-1f);
    const u64 C_ONE = bc(1.0f);

    u64 macc[RPT] = {0ULL, 0ULL};
    u64 qacc[RPT] = {0ULL, 0ULL};

    for (int chunk = 0; chunk < NCHUNK; ++chunk) {
        __syncthreads();
        {   // stage param chunk: CHUNK i x 8 og x 13 uint4 (coalesced)
            const uint4* src = reinterpret_cast<const uint4*>(
                g_params + (i0 + chunk * CHUNK) * 8 * RECF);
            for (int idx = tid; idx < CHUNK * 8 * 13; idx += 128) {
                int rrec = idx / 13, k4 = idx - rrec * 13;
                uint4 v4 = src[idx];
                *reinterpret_cast<uint4*>(&prm[rrec * RECS + 4 * k4]) = v4;
            }
        }
        __syncthreads();

        for (int ii = 0; ii < CHUNK; ++ii) {
            const int il = chunk * CHUNK + ii;

            // record -> registers once, reused for RPT rows
            const uint4* Rq = reinterpret_cast<const uint4*>(&prm[(ii * 8 + og) * RECS]);
            u64 P[RKU];
#pragma unroll
            for (int k4 = 0; k4 < 13; ++k4) {
                uint4 q = Rq[k4];
                P[2 * k4]     = pk2(q.x, q.y);
                P[2 * k4 + 1] = pk2(q.z, q.w);
            }
            const u64 l2 = P[0];

#pragma unroll
            for (int rr = 0; rr < RPT; ++rr) {
                const float2 msv = ms_sm[il][rp * 2 + rr];
                const u64 MU = bc(msv.x);
                const u64 S2 = bc(msv.y);

                // d = l2 + s2; r = 1/sqrt(d) via MUFU per half
                u64 d = f2add(l2, S2);
                unsigned dlo, dhi; upk(d, dlo, dhi);
                float rlo = rsqrtf(__uint_as_float(dlo));
                float rhi = rsqrtf(__uint_as_float(dhi));
                u64 r   = pk2(__float_as_uint(rlo), __float_as_uint(rhi));
                u64 rsq = f2mul(r, r);                   // 1/d
                const u64 ccp = f2mul(rsq, C_NHL2E);     // -log2e/(2d)

                // 5 expected-kernel values: e_p = 2^( ccp * (mu - z_p)^2 )
                u64 e[NP];
#pragma unroll
                for (int p = 0; p < NP; ++p) {
                    u64 t  = f2add(MU, P[1 + p]);        // P holds -z
                    u64 t2 = f2mul(t, t);
                    u64 y  = f2mul(t2, ccp);
                    u64 zf = f2add(y, C_MAGIC);
                    unsigned zlo, zhi; upk(zf, zlo, zhi);
                    u64 sc = pk2((zlo << 23) + 0x3F800000u, (zhi << 23) + 0x3F800000u);
                    u64 nf = f2add(zf, C_NMAGIC);
                    u64 f  = f2fma(nf, C_N1, y);
                    u64 pp = f2fma(C_P5, f, C_P4);
                    pp = f2fma(pp, f, C_P3);
                    pp = f2fma(pp, f, C_P2);
                    pp = f2fma(pp, f, C_P1);
                    pp = f2fma(pp, f, C_ONE);
                    e[p] = f2mul(pp, sc);
                }

                // l*mean: e . alpha'  (alpha' = l*alpha at P[6..10])
                u64 me = f2mul(e[0], P[6]);
                me = f2fma(e[1], P[7],  me);
                me = f2fma(e[2], P[8],  me);
                me = f2fma(e[3], P[9],  me);
                me = f2fma(e[4], P[10], me);

                // l2*qKq = ||W' e||^2  (W' = l*W lower-tri at P[11..25])
                u64 v0 = f2mul(P[11], e[0]);
                u64 v1 = f2fma(P[13], e[1], f2mul(P[12], e[0]));
                u64 v2 = f2fma(P[16], e[2], f2fma(P[15], e[1], f2mul(P[14], e[0])));
                u64 v3 = f2fma(P[20], e[3], f2fma(P[19], e[2],
                         f2fma(P[18], e[1], f2mul(P[17], e[0]))));
                u64 v4 = f2fma(P[25], e[4], f2fma(P[24], e[3],
                         f2fma(P[23], e[2], f2fma(P[22], e[1], f2mul(P[21], e[0])))));
                u64 qk = f2mul(v0, v0);
                qk = f2fma(v1, v1, qk);
                qk = f2fma(v2, v2, qk);
                qk = f2fma(v3, v3, qk);
                qk = f2fma(v4, v4, qk);

                macc[rr] = f2fma(me, r,   macc[rr]);   // s*mean   = r * (l*mean)
                qacc[rr] = f2fma(qk, rsq, qacc[rr]);   // ss*qKq   = (1/d)*(l2*qKq)
            }
        }
    }

#pragma unroll
    for (int rr = 0; rr < RPT; ++rr) {
        const int r = row0 + rp * 2 + rr;
        unsigned mlo, mhi, qlo, qhi;
        upk(macc[rr], mlo, mhi); upk(qacc[rr], qlo, qhi);
        g_part[(split * NROWS + r) * 8 + og] =
            make_float4(__uint_as_float(mlo), __uint_as_float(mhi),
                        __uint_as_float(qlo), __uint_as_float(qhi));
    }
}

// ---------------- reduce: combine the 2 i-splits ----------------
__global__ __launch_bounds__(256) void gp_reduce(float* __restrict__ out) {
    int idx = blockIdx.x * 256 + threadIdx.x;       // over NROWS*8
    if (idx >= NROWS * 8) return;
    float4 a = g_part[idx];
    float4 b = g_part[NROWS * 8 + idx];
    float2 mo = make_float2(a.x + b.x, a.y + b.y);
    float2 vo = make_float2(fmaxf(72.0f - (a.z + b.z), 1e-6f),
                            fmaxf(72.0f - (a.w + b.w), 1e-6f));
    reinterpret_cast<float2*>(out)[idx] = mo;
    reinterpret_cast<float2*>(out + NROWS * OCH)[idx] = vo;
}

extern "C" void kernel_launch(void* const* d_in, const int* in_sizes, int n_in,
                              void* d_out, int out_size) {
    const float* xm  = (const float*)d_in[0];  // x_mean [8,32,32,8]
    const float* xv  = (const float*)d_in[1];  // x_var
    const float* z   = (const float*)d_in[2];  // [16,72,5]
    const float* h   = (const float*)d_in[3];  // [16,72,5]
    const float* rlp = (const float*)d_in[4];  // [16,72]
    float* out = (float*)d_out;                // [m (131072) | v (131072)]

    gp_pre<<<36, 32>>>(z, h, rlp);
    gp_main<<<dim3(NROWS / ROWSB, ISPLIT), 128>>>(xm, xv);
    gp_reduce<<<NROWS * 8 / 256, 256>>>(out);
}

// round 6
// speedup vs baseline: 2.3701x; 1.1950x over previous
#include <cuda_runtime.h>

// ---- problem constants ----
#define NROWS   8192      // N * OH * OW = 8*32*32
#define IDIM    72        // IC*KH*KW
#define OCH     16
#define NP      5
#define RKU     26        // u64 entries per record: l2, negz*5, alpha'*5, W'*15
#define RECF    52        // floats per record in global (= RKU*2) = 13 uint4
#define RECS    60        // smem float stride: og*60%32 distinct -> conflict-free
#define ROWSB   32        // rows per CTA
#define RPT     2         // rows per thread
#define ISPLIT  4
#define IQ      18        // IDIM / ISPLIT

// global param table: [i][og][RECF] floats, og = o>>1, float2-interleaved over lane=o&1
__device__ float g_params[IDIM * 8 * RECF];
// partial sums: [split][row][og] -> float4(m.lo, m.hi, q.lo, q.hi)
__device__ float4 g_part[ISPLIT * NROWS * 8];

typedef unsigned long long u64;

// ---------------- packed f32x2 helpers ----------------
__device__ __forceinline__ u64 pk2(unsigned lo, unsigned hi) {
    u64 d; asm("mov.b64 %0,{%1,%2};" : "=l"(d) : "r"(lo), "r"(hi)); return d;
}
__device__ __forceinline__ void upk(u64 v, unsigned& lo, unsigned& hi) {
    asm("mov.b64 {%0,%1},%2;" : "=r"(lo), "=r"(hi) : "l"(v));
}
__device__ __forceinline__ u64 bc(float f) {
    unsigned u = __float_as_uint(f); return pk2(u, u);
}
__device__ __forceinline__ u64 f2fma(u64 a, u64 b, u64 c) {
    u64 d; asm("fma.rn.f32x2 %0,%1,%2,%3;" : "=l"(d) : "l"(a), "l"(b), "l"(c)); return d;
}
__device__ __forceinline__ u64 f2mul(u64 a, u64 b) {
    u64 d; asm("mul.rn.f32x2 %0,%1,%2;" : "=l"(d) : "l"(a), "l"(b)); return d;
}
__device__ __forceinline__ u64 f2add(u64 a, u64 b) {
    u64 d; asm("add.rn.f32x2 %0,%1,%2;" : "=l"(d) : "l"(a), "l"(b)); return d;
}

// ---------------- precompute: fp32 solve + one fp64-residual refinement ----------------
__global__ void gp_pre(const float* __restrict__ z,
                       const float* __restrict__ h,
                       const float* __restrict__ raw_l) {
    int pid = blockIdx.x * blockDim.x + threadIdx.x;
    if (pid >= IDIM * OCH) return;
    int o = pid / IDIM, i = pid - o * IDIM;
    int oi = o * IDIM + i;

    float x   = raw_l[oi];
    float spf = log1pf(expf(x));     // softplus, fp32 like reference
    float l2f = spf * spf;

    float zz[NP], hf[NP];
#pragma unroll
    for (int p = 0; p < NP; ++p) {
        zz[p] = z[oi * NP + p];
        hf[p] = h[oi * NP + p];
    }

    // K in fp32 (matches reference formation); exact fp64 copy for refinement
    float  Kf[NP][NP];
    double Kd[NP][NP];
#pragma unroll
    for (int p = 0; p < NP; ++p)
#pragma unroll
        for (int q = 0; q < NP; ++q) {
            float dz = zz[p] - zz[q];
            float v = expf(-0.5f * dz * dz / l2f) + (p == q ? 1e-4f : 0.0f);
            Kf[p][q] = v; Kd[p][q] = (double)v;
        }

    // fp32 Cholesky K = L L^T (rsqrt + 1 Newton; all lat-4 ops)
    float L[NP][NP], rdiag[NP];
#pragma unroll
    for (int j = 0; j < NP; ++j) {
        float s = Kf[j][j];
#pragma unroll
        for (int k = 0; k < NP; ++k) if (k < j) s = fmaf(-L[j][k], L[j][k], s);
        float r = rsqrtf(s);
        r = r * fmaf(-0.5f * s * r, r, 1.5f);
        rdiag[j] = r;
        L[j][j] = s * r;
#pragma unroll
        for (int rr = 0; rr < NP; ++rr) if (rr > j) {
            float t = Kf[rr][j];
#pragma unroll
            for (int k = 0; k < NP; ++k) if (k < j) t = fmaf(-L[rr][k], L[j][k], t);
            L[rr][j] = t * r;
        }
    }
    // W = L^{-1} (lower) in fp32: K^{-1} = W^T W
    float W[NP][NP];
#pragma unroll
    for (int j = 0; j < NP; ++j) {
        W[j][j] = rdiag[j];
#pragma unroll
        for (int rr = 0; rr < NP; ++rr) if (rr > j) {
            float t = 0.0f;
#pragma unroll
            for (int k = 0; k < NP; ++k) if (k >= j && k < rr) t = fmaf(L[rr][k], W[k][j], t);
            W[rr][j] = -t * rdiag[rr];
        }
    }

    // alpha0 = W^T (W h) in fp32
    float t1[NP], a0[NP];
#pragma unroll
    for (int p = 0; p < NP; ++p) {
        float s = 0.0f;
#pragma unroll
        for (int q = 0; q < NP; ++q) if (q <= p) s = fmaf(W[p][q], hf[q], s);
        t1[p] = s;
    }
#pragma unroll
    for (int q = 0; q < NP; ++q) {
        float s = 0.0f;
#pragma unroll
        for (int p = 0; p < NP; ++p) if (p >= q) s = fmaf(W[p][q], t1[p], s);
        a0[q] = s;
    }
    // one iterative refinement: r = h - K a0 (fp64), da = W^T(W r) (fp32)
    float rf[NP];
#pragma unroll
    for (int p = 0; p < NP; ++p) {
        double s = (double)hf[p];
#pragma unroll
        for (int q = 0; q < NP; ++q) s = fma(-Kd[p][q], (double)a0[q], s);
        rf[p] = (float)s;
    }
    float t2[NP], al[NP];
#pragma unroll
    for (int p = 0; p < NP; ++p) {
        float s = 0.0f;
#pragma unroll
        for (int q = 0; q < NP; ++q) if (q <= p) s = fmaf(W[p][q], rf[q], s);
        t2[p] = s;
    }
#pragma unroll
    for (int q = 0; q < NP; ++q) {
        float s = a0[q];
#pragma unroll
        for (int p = 0; p < NP; ++p) if (p >= q) s = fmaf(W[p][q], t2[p], s);
        al[q] = s;
    }

    // record (float2-interleaved): l2, -z*5, (l*alpha)*5, (l*W)*15
    int og = o >> 1, lane = o & 1;
    float* rec = g_params + (i * 8 + og) * RECF + lane;
    rec[0] = l2f;
#pragma unroll
    for (int p = 0; p < NP; ++p) rec[(1 + p) * 2] = -zz[p];
#pragma unroll
    for (int p = 0; p < NP; ++p) rec[(6 + p) * 2] = spf * al[p];
#pragma unroll
    for (int p = 0; p < NP; ++p)
#pragma unroll
        for (int q = 0; q < NP; ++q) if (q <= p)
            rec[(11 + p * (p + 1) / 2 + q) * 2] = spf * W[p][q];
}

// ---------------- main: 4-way i-split, 2 rows/thread, records in registers ----------------
__global__ __launch_bounds__(128) void gp_main(const float* __restrict__ xm,
                                               const float* __restrict__ xv) {
    __shared__ __align__(16) float2 ms_sm[IQ][ROWSB + 1];   // (mu, s2)
    __shared__ __align__(16) float  prm[IQ * 8 * RECS];

    const int tid   = threadIdx.x;
    const int row0  = blockIdx.x * ROWSB;
    const int split = blockIdx.y;
    const int i0    = split * IQ;

    // stage im2col(mu,s2) for this CTA's rows, this split's i-range
    for (int idx = tid; idx < IQ * ROWSB; idx += 128) {
        int il = idx >> 5, rlocal = idx & 31;
        int i = i0 + il;
        int c = i / 9, rem = i - c * 9;
        int kh = rem / 3, kw = rem - kh * 3;
        int r = row0 + rlocal;
        int n = r >> 10, oh = (r >> 5) & 31, ow = r & 31;
        int ih = oh + kh - 1, iw = ow + kw - 1;
        float m = 0.0f, v = 0.0f;
        if ((unsigned)ih < 32u && (unsigned)iw < 32u) {
            int g = ((n * 32 + ih) * 32 + iw) * 8 + c;
            m = xm[g]; v = xv[g];
        }
        ms_sm[il][rlocal] = make_float2(m, v);
    }
    // stage this split's param records: IQ x 8 x 13 uint4, contiguous in global
    {
        const uint4* src = reinterpret_cast<const uint4*>(g_params + i0 * 8 * RECF);
        for (int idx = tid; idx < IQ * 8 * 13; idx += 128) {
            int rrec = idx / 13, k4 = idx - rrec * 13;
            uint4 v4 = src[idx];
            *reinterpret_cast<uint4*>(&prm[rrec * RECS + 4 * k4]) = v4;
        }
    }
    __syncthreads();

    const int og = tid & 7;          // 8 o-pairs
    const int rp = tid >> 3;         // 16 row-pairs -> rows rp*2, rp*2+1

    // packed constants
    const u64 C_N1     = bc(-1.0f);
    const u64 C_MAGIC  = bc(12582912.0f);
    const u64 C_NHL2E  = bc(-0.7213475204444817f);   // -0.5*log2(e)
    const u64 C_P5 = bc(1.33335581464284e-3f);
    const u64 C_P4 = bc(9.61812910762848e-3f);
    const u64 C_P3 = bc(5.55041086648216e-2f);
    const u64 C_P2 = bc(2.40226506959101e-1f);
    const u64 C_P1 = bc(6.93147180559945e-1f);
    const u64 C_ONE = bc(1.0f);

    u64 macc[RPT] = {0ULL, 0ULL};
    u64 qacc[RPT] = {0ULL, 0ULL};

    for (int il = 0; il < IQ; ++il) {
        // record -> registers once, reused for RPT rows
        const uint4* Rq = reinterpret_cast<const uint4*>(&prm[(il * 8 + og) * RECS]);
        u64 P[RKU];
#pragma unroll
        for (int k4 = 0; k4 < 13; ++k4) {
            uint4 q = Rq[k4];
            P[2 * k4]     = pk2(q.x, q.y);
            P[2 * k4 + 1] = pk2(q.z, q.w);
        }
        const u64 l2 = P[0];

#pragma unroll
        for (int rr = 0; rr < RPT; ++rr) {
            const float2 msv = ms_sm[il][rp * 2 + rr];
            const u64 MU = bc(msv.x);
            const u64 S2 = bc(msv.y);

            // d = l2 + s2; r = 1/sqrt(d) via MUFU per half
            u64 d = f2add(l2, S2);
            unsigned dlo, dhi; upk(d, dlo, dhi);
            float rlo = rsqrtf(__uint_as_float(dlo));
            float rhi = rsqrtf(__uint_as_float(dhi));
            u64 r   = pk2(__float_as_uint(rlo), __float_as_uint(rhi));
            u64 rsq = f2mul(r, r);                   // 1/d
            const u64 ccp = f2mul(rsq, C_NHL2E);     // -log2e/(2d)

            // e_p = 2^( ccp*(mu-z_p)^2 ): magic-round folded into FMAs,
            // exponent applied with integer adds on the ALU pipe
            u64 e[NP];
#pragma unroll
            for (int p = 0; p < NP; ++p) {
                u64 t  = f2add(MU, P[1 + p]);        // P holds -z
                u64 t2 = f2mul(t, t);
                u64 zf = f2fma(t2, ccp, C_MAGIC);    // MAGIC + n
                u64 nn = f2fma(zf, C_N1, C_MAGIC);   // -n (float)
                u64 f  = f2fma(t2, ccp, nn);         // y - n, in [-0.5, 0.5]
                u64 pp = f2fma(C_P5, f, C_P4);
                pp = f2fma(pp, f, C_P3);
                pp = f2fma(pp, f, C_P2);
                pp = f2fma(pp, f, C_P1);
                pp = f2fma(pp, f, C_ONE);
                unsigned zlo, zhi; upk(zf, zlo, zhi);
                unsigned plo, phi; upk(pp, plo, phi);
                // bits(pp) + (n<<23): exact scale by 2^n (low 9 bits of magic are 0)
                e[p] = pk2(plo + (zlo << 23), phi + (zhi << 23));
            }

            // l*mean: e . alpha'  (alpha' = l*alpha at P[6..10])
            u64 me = f2mul(e[0], P[6]);
            me = f2fma(e[1], P[7],  me);
            me = f2fma(e[2], P[8],  me);
            me = f2fma(e[3], P[9],  me);
            me = f2fma(e[4], P[10], me);

            // l2*qKq = ||W' e||^2  (W' = l*W lower-tri at P[11..25])
            u64 v0 = f2mul(P[11], e[0]);
            u64 v1 = f2fma(P[13], e[1], f2mul(P[12], e[0]));
            u64 v2 = f2fma(P[16], e[2], f2fma(P[15], e[1], f2mul(P[14], e[0])));
            u64 v3 = f2fma(P[20], e[3], f2fma(P[19], e[2],
                     f2fma(P[18], e[1], f2mul(P[17], e[0]))));
            u64 v4 = f2fma(P[25], e[4], f2fma(P[24], e[3],
                     f2fma(P[23], e[2], f2fma(P[22], e[1], f2mul(P[21], e[0])))));
            u64 qk = f2mul(v0, v0);
            qk = f2fma(v1, v1, qk);
            qk = f2fma(v2, v2, qk);
            qk = f2fma(v3, v3, qk);
            qk = f2fma(v4, v4, qk);

            macc[rr] = f2fma(me, r,   macc[rr]);   // s*mean = r * (l*mean)
            qacc[rr] = f2fma(qk, rsq, qacc[rr]);   // (1/d) * (l2*qKq)
        }
    }

#pragma unroll
    for (int rr = 0; rr < RPT; ++rr) {
        const int r = row0 + rp * 2 + rr;
        unsigned mlo, mhi, qlo, qhi;
        upk(macc[rr], mlo, mhi); upk(qacc[rr], qlo, qhi);
        g_part[(split * NROWS + r) * 8 + og] =
            make_float4(__uint_as_float(mlo), __uint_as_float(mhi),
                        __uint_as_float(qlo), __uint_as_float(qhi));
    }
}

// ---------------- reduce: combine the 4 i-splits ----------------
__global__ __launch_bounds__(256) void gp_reduce(float* __restrict__ out) {
    int idx = blockIdx.x * 256 + threadIdx.x;       // over NROWS*8
    if (idx >= NROWS * 8) return;
    float4 a = g_part[idx];
    float4 b = g_part[NROWS * 8 + idx];
    float4 c = g_part[2 * NROWS * 8 + idx];
    float4 e = g_part[3 * NROWS * 8 + idx];
    float2 mo = make_float2((a.x + b.x) + (c.x + e.x), (a.y + b.y) + (c.y + e.y));
    float qs0 = (a.z + b.z) + (c.z + e.z);
    float qs1 = (a.w + b.w) + (c.w + e.w);
    float2 vo = make_float2(fmaxf(72.0f - qs0, 1e-6f), fmaxf(72.0f - qs1, 1e-6f));
    reinterpret_cast<float2*>(out)[idx] = mo;
    reinterpret_cast<float2*>(out + NROWS * OCH)[idx] = vo;
}

extern "C" void kernel_launch(void* const* d_in, const int* in_sizes, int n_in,
                              void* d_out, int out_size) {
    const float* xm  = (const float*)d_in[0];  // x_mean [8,32,32,8]
    const float* xv  = (const float*)d_in[1];  // x_var
    const float* z   = (const float*)d_in[2];  // [16,72,5]
    const float* h   = (const float*)d_in[3];  // [16,72,5]
    const float* rlp = (const float*)d_in[4];  // [16,72]
    float* out = (float*)d_out;                // [m (131072) | v (131072)]

    gp_pre<<<36, 32>>>(z, h, rlp);
    gp_main<<<dim3(NROWS / ROWSB, ISPLIT), 128>>>(xm, xv);
    gp_reduce<<<NROWS * 8 / 256, 256>>>(out);
}

// round 7
// speedup vs baseline: 2.5125x; 1.0601x over previous
#include <cuda_runtime.h>

// ---- problem constants ----
#define NROWS   8192      // N * OH * OW = 8*32*32
#define IDIM    72        // IC*KH*KW
#define OCH     16
#define NP      5
#define RKU     26        // u64 entries per record: l2, negz*5, alpha'*5, W'*15
#define RECF    52        // floats per record in global (= RKU*2) = 13 uint4
#define RECS    60        // smem float stride: og*60%32 distinct -> conflict-free
#define ROWSB   64        // rows per CTA
#define RPT     4         // rows per thread
#define ISPLIT  4
#define IQ      18        // IDIM / ISPLIT

// global param table: [i][og][RECF] floats, og = o>>1, float2-interleaved over lane=o&1
__device__ float g_params[IDIM * 8 * RECF];
// partial sums: [split][row][og] -> float4(m.lo, m.hi, q.lo, q.hi)
__device__ float4 g_part[ISPLIT * NROWS * 8];

typedef unsigned long long u64;

// ---------------- packed f32x2 + fast-math helpers ----------------
__device__ __forceinline__ u64 pk2(unsigned lo, unsigned hi) {
    u64 d; asm("mov.b64 %0,{%1,%2};" : "=l"(d) : "r"(lo), "r"(hi)); return d;
}
__device__ __forceinline__ void upk(u64 v, unsigned& lo, unsigned& hi) {
    asm("mov.b64 {%0,%1},%2;" : "=r"(lo), "=r"(hi) : "l"(v));
}
__device__ __forceinline__ u64 bc(float f) {
    unsigned u = __float_as_uint(f); return pk2(u, u);
}
__device__ __forceinline__ u64 f2fma(u64 a, u64 b, u64 c) {
    u64 d; asm("fma.rn.f32x2 %0,%1,%2,%3;" : "=l"(d) : "l"(a), "l"(b), "l"(c)); return d;
}
__device__ __forceinline__ u64 f2mul(u64 a, u64 b) {
    u64 d; asm("mul.rn.f32x2 %0,%1,%2;" : "=l"(d) : "l"(a), "l"(b)); return d;
}
__device__ __forceinline__ u64 f2add(u64 a, u64 b) {
    u64 d; asm("add.rn.f32x2 %0,%1,%2;" : "=l"(d) : "l"(a), "l"(b)); return d;
}
__device__ __forceinline__ float ex2f(float x) {
    float y; asm("ex2.approx.f32 %0,%1;" : "=f"(y) : "f"(x)); return y;
}
__device__ __forceinline__ float rcpf(float x) {
    float y; asm("rcp.approx.f32 %0,%1;" : "=f"(y) : "f"(x)); return y;
}

// ---------------- precompute: fast-K formation, fp32 solve + fp64 refinement ----------------
__global__ void gp_pre(const float* __restrict__ z,
                       const float* __restrict__ h,
                       const float* __restrict__ raw_l) {
    int pid = blockIdx.x * blockDim.x + threadIdx.x;
    if (pid >= IDIM * OCH) return;
    int o = pid / IDIM, i = pid - o * IDIM;
    int oi = o * IDIM + i;

    float x   = raw_l[oi];
    float spf = log1pf(expf(x));     // softplus, precise fp32 (matches reference)
    float l2f = spf * spf;
    float cK  = -0.7213475204444817f * rcpf(l2f);   // -log2e/(2 l2)

    float zz[NP], hf[NP];
#pragma unroll
    for (int p = 0; p < NP; ++p) {
        zz[p] = z[oi * NP + p];
        hf[p] = h[oi * NP + p];
    }

    // K via ex2.approx (2ulp); fp64 copy for the refinement residual
    float  Kf[NP][NP];
    double Kd[NP][NP];
#pragma unroll
    for (int p = 0; p < NP; ++p)
#pragma unroll
        for (int q = 0; q < NP; ++q) {
            float dz = zz[p] - zz[q];
            float v = ex2f(dz * dz * cK) + (p == q ? 1e-4f : 0.0f);
            Kf[p][q] = v; Kd[p][q] = (double)v;
        }

    // fp32 Cholesky K = L L^T (rsqrt + 1 Newton)
    float L[NP][NP], rdiag[NP];
#pragma unroll
    for (int j = 0; j < NP; ++j) {
        float s = Kf[j][j];
#pragma unroll
        for (int k = 0; k < NP; ++k) if (k < j) s = fmaf(-L[j][k], L[j][k], s);
        float r = rsqrtf(s);
        r = r * fmaf(-0.5f * s * r, r, 1.5f);
        rdiag[j] = r;
        L[j][j] = s * r;
#pragma unroll
        for (int rr = 0; rr < NP; ++rr) if (rr > j) {
            float t = Kf[rr][j];
#pragma unroll
            for (int k = 0; k < NP; ++k) if (k < j) t = fmaf(-L[rr][k], L[j][k], t);
            L[rr][j] = t * r;
        }
    }
    // W = L^{-1} (lower): K^{-1} = W^T W
    float W[NP][NP];
#pragma unroll
    for (int j = 0; j < NP; ++j) {
        W[j][j] = rdiag[j];
#pragma unroll
        for (int rr = 0; rr < NP; ++rr) if (rr > j) {
            float t = 0.0f;
#pragma unroll
            for (int k = 0; k < NP; ++k) if (k >= j && k < rr) t = fmaf(L[rr][k], W[k][j], t);
            W[rr][j] = -t * rdiag[rr];
        }
    }

    // alpha0 = W^T (W h), then one fp64-residual refinement
    float t1[NP], a0[NP];
#pragma unroll
    for (int p = 0; p < NP; ++p) {
        float s = 0.0f;
#pragma unroll
        for (int q = 0; q < NP; ++q) if (q <= p) s = fmaf(W[p][q], hf[q], s);
        t1[p] = s;
    }
#pragma unroll
    for (int q = 0; q < NP; ++q) {
        float s = 0.0f;
#pragma unroll
        for (int p = 0; p < NP; ++p) if (p >= q) s = fmaf(W[p][q], t1[p], s);
        a0[q] = s;
    }
    float rf[NP];
#pragma unroll
    for (int p = 0; p < NP; ++p) {
        double s = (double)hf[p];
#pragma unroll
        for (int q = 0; q < NP; ++q) s = fma(-Kd[p][q], (double)a0[q], s);
        rf[p] = (float)s;
    }
    float t2[NP], al[NP];
#pragma unroll
    for (int p = 0; p < NP; ++p) {
        float s = 0.0f;
#pragma unroll
        for (int q = 0; q < NP; ++q) if (q <= p) s = fmaf(W[p][q], rf[q], s);
        t2[p] = s;
    }
#pragma unroll
    for (int q = 0; q < NP; ++q) {
        float s = a0[q];
#pragma unroll
        for (int p = 0; p < NP; ++p) if (p >= q) s = fmaf(W[p][q], t2[p], s);
        al[q] = s;
    }

    // record (float2-interleaved): l2, -z*5, (l*alpha)*5, (l*W)*15
    int og = o >> 1, lane = o & 1;
    float* rec = g_params + (i * 8 + og) * RECF + lane;
    rec[0] = l2f;
#pragma unroll
    for (int p = 0; p < NP; ++p) rec[(1 + p) * 2] = -zz[p];
#pragma unroll
    for (int p = 0; p < NP; ++p) rec[(6 + p) * 2] = spf * al[p];
#pragma unroll
    for (int p = 0; p < NP; ++p)
#pragma unroll
        for (int q = 0; q < NP; ++q) if (q <= p)
            rec[(11 + p * (p + 1) / 2 + q) * 2] = spf * W[p][q];
}

// ---------------- main: 4-way i-split, 4 rows/thread, EX2-based exps ----------------
__global__ __launch_bounds__(128) void gp_main(const float* __restrict__ xm,
                                               const float* __restrict__ xv) {
    __shared__ __align__(16) float2 ms_sm[IQ][ROWSB + 1];   // (mu, s2)
    __shared__ __align__(16) float  prm[IQ * 8 * RECS];

    const int tid   = threadIdx.x;
    const int row0  = blockIdx.x * ROWSB;
    const int split = blockIdx.y;
    const int i0    = split * IQ;

    // stage im2col(mu,s2) for this CTA's rows, this split's i-range
    for (int idx = tid; idx < IQ * ROWSB; idx += 128) {
        int il = idx >> 6, rlocal = idx & 63;
        int i = i0 + il;
        int c = i / 9, rem = i - c * 9;
        int kh = rem / 3, kw = rem - kh * 3;
        int r = row0 + rlocal;
        int n = r >> 10, oh = (r >> 5) & 31, ow = r & 31;
        int ih = oh + kh - 1, iw = ow + kw - 1;
        float m = 0.0f, v = 0.0f;
        if ((unsigned)ih < 32u && (unsigned)iw < 32u) {
            int g = ((n * 32 + ih) * 32 + iw) * 8 + c;
            m = xm[g]; v = xv[g];
        }
        ms_sm[il][rlocal] = make_float2(m, v);
    }
    // stage this split's param records: IQ x 8 x 13 uint4, contiguous in global
    {
        const uint4* src = reinterpret_cast<const uint4*>(g_params + i0 * 8 * RECF);
        for (int idx = tid; idx < IQ * 8 * 13; idx += 128) {
            int rrec = idx / 13, k4 = idx - rrec * 13;
            uint4 v4 = src[idx];
            *reinterpret_cast<uint4*>(&prm[rrec * RECS + 4 * k4]) = v4;
        }
    }
    __syncthreads();

    const int og = tid & 7;          // 8 o-pairs
    const int rp = tid >> 3;         // 16 row-quads -> rows rp*4 .. rp*4+3

    const u64 C_NHL2E = bc(-0.7213475204444817f);   // -0.5*log2(e)

    u64 macc[RPT] = {0ULL, 0ULL, 0ULL, 0ULL};
    u64 qacc[RPT] = {0ULL, 0ULL, 0ULL, 0ULL};

    for (int il = 0; il < IQ; ++il) {
        // record -> registers once, reused for RPT rows
        const uint4* Rq = reinterpret_cast<const uint4*>(&prm[(il * 8 + og) * RECS]);
        u64 P[RKU];
#pragma unroll
        for (int k4 = 0; k4 < 13; ++k4) {
            uint4 q = Rq[k4];
            P[2 * k4]     = pk2(q.x, q.y);
            P[2 * k4 + 1] = pk2(q.z, q.w);
        }
        const u64 l2 = P[0];

#pragma unroll
        for (int rr = 0; rr < RPT; ++rr) {
            const float2 msv = ms_sm[il][rp * RPT + rr];
            const u64 MU = bc(msv.x);
            const u64 S2 = bc(msv.y);

            // d = l2 + s2; r = 1/sqrt(d) via MUFU per half
            u64 d = f2add(l2, S2);
            unsigned dlo, dhi; upk(d, dlo, dhi);
            float rlo = rsqrtf(__uint_as_float(dlo));
            float rhi = rsqrtf(__uint_as_float(dhi));
            u64 r   = pk2(__float_as_uint(rlo), __float_as_uint(rhi));
            u64 rsq = f2mul(r, r);                   // 1/d
            const u64 ccp = f2mul(rsq, C_NHL2E);     // -log2e/(2d)

            // e_p = 2^( ccp*(mu-z_p)^2 ) via MUFU EX2 per half
            u64 e[NP];
#pragma unroll
            for (int p = 0; p < NP; ++p) {
                u64 t  = f2add(MU, P[1 + p]);        // P holds -z
                u64 t2 = f2mul(t, t);
                u64 y  = f2mul(t2, ccp);
                unsigned ylo, yhi; upk(y, ylo, yhi);
                float elo = ex2f(__uint_as_float(ylo));
                float ehi = ex2f(__uint_as_float(yhi));
                e[p] = pk2(__float_as_uint(elo), __float_as_uint(ehi));
            }

            // l*mean: e . alpha'  (alpha' = l*alpha at P[6..10])
            u64 me = f2mul(e[0], P[6]);
            me = f2fma(e[1], P[7],  me);
            me = f2fma(e[2], P[8],  me);
            me = f2fma(e[3], P[9],  me);
            me = f2fma(e[4], P[10], me);

            // l2*qKq = ||W' e||^2  (W' = l*W lower-tri at P[11..25])
            u64 v0 = f2mul(P[11], e[0]);
            u64 v1 = f2fma(P[13], e[1], f2mul(P[12], e[0]));
            u64 v2 = f2fma(P[16], e[2], f2fma(P[15], e[1], f2mul(P[14], e[0])));
            u64 v3 = f2fma(P[20], e[3], f2fma(P[19], e[2],
                     f2fma(P[18], e[1], f2mul(P[17], e[0]))));
            u64 v4 = f2fma(P[25], e[4], f2fma(P[24], e[3],
                     f2fma(P[23], e[2], f2fma(P[22], e[1], f2mul(P[21], e[0])))));
            u64 qk = f2mul(v0, v0);
            qk = f2fma(v1, v1, qk);
            qk = f2fma(v2, v2, qk);
            qk = f2fma(v3, v3, qk);
            qk = f2fma(v4, v4, qk);

            macc[rr] = f2fma(me, r,   macc[rr]);   // s*mean = r * (l*mean)
            qacc[rr] = f2fma(qk, rsq, qacc[rr]);   // (1/d) * (l2*qKq)
        }
    }

#pragma unroll
    for (int rr = 0; rr < RPT; ++rr) {
        const int r = row0 + rp * RPT + rr;
        unsigned mlo, mhi, qlo, qhi;
        upk(macc[rr], mlo, mhi); upk(qacc[rr], qlo, qhi);
        g_part[(split * NROWS + r) * 8 + og] =
            make_float4(__uint_as_float(mlo), __uint_as_float(mhi),
                        __uint_as_float(qlo), __uint_as_float(qhi));
    }
}

// ---------------- reduce: combine the 4 i-splits ----------------
__global__ __launch_bounds__(256) void gp_reduce(float* __restrict__ out) {
    int idx = blockIdx.x * 256 + threadIdx.x;       // over NROWS*8
    if (idx >= NROWS * 8) return;
    float4 a = g_part[idx];
    float4 b = g_part[NROWS * 8 + idx];
    float4 c = g_part[2 * NROWS * 8 + idx];
    float4 e = g_part[3 * NROWS * 8 + idx];
    float2 mo = make_float2((a.x + b.x) + (c.x + e.x), (a.y + b.y) + (c.y + e.y));
    float qs0 = (a.z + b.z) + (c.z + e.z);
    float qs1 = (a.w + b.w) + (c.w + e.w);
    float2 vo = make_float2(fmaxf(72.0f - qs0, 1e-6f), fmaxf(72.0f - qs1, 1e-6f));
    reinterpret_cast<float2*>(out)[idx] = mo;
    reinterpret_cast<float2*>(out + NROWS * OCH)[idx] = vo;
}

extern "C" void kernel_launch(void* const* d_in, const int* in_sizes, int n_in,
                              void* d_out, int out_size) {
    const float* xm  = (const float*)d_in[0];  // x_mean [8,32,32,8]
    const float* xv  = (const float*)d_in[1];  // x_var
    const float* z   = (const float*)d_in[2];  // [16,72,5]
    const float* h   = (const float*)d_in[3];  // [16,72,5]
    const float* rlp = (const float*)d_in[4];  // [16,72]
    float* out = (float*)d_out;                // [m (131072) | v (131072)]

    gp_pre<<<36, 32>>>(z, h, rlp);
    gp_main<<<dim3(NROWS / ROWSB, ISPLIT), 128>>>(xm, xv);
    gp_reduce<<<NROWS * 8 / 256, 256>>>(out);
}

// round 9
// speedup vs baseline: 2.7577x; 1.0976x over previous
#include <cuda_runtime.h>

// ---- problem constants ----
#define NROWS   8192      // N * OH * OW = 8*32*32
#define IDIM    72        // IC*KH*KW
#define OCH     16
#define NP      5
#define RKU     26        // u64 entries per record: l2, negz*5, alpha'*5, W'*15
#define RECF    52        // floats per record in global (= RKU*2) = 13 uint4
#define RECS    60        // smem float stride: og*60%32 distinct -> conflict-free
#define ROWSB   64        // rows per CTA
#define RPT     4         // rows per thread
#define ISPLIT  6
#define IQ      12        // IDIM / ISPLIT

// global param table: [i][og][RECF] floats, og = o>>1, float2-interleaved over lane=o&1
__device__ float g_params[IDIM * 8 * RECF];
// partial sums: [split][row][og] -> float4(m.lo, m.hi, q.lo, q.hi)
__device__ float4 g_part[ISPLIT * NROWS * 8];

typedef unsigned long long u64;

// ---------------- packed f32x2 + fast-math helpers ----------------
__device__ __forceinline__ u64 pk2(unsigned lo, unsigned hi) {
    u64 d; asm("mov.b64 %0,{%1,%2};" : "=l"(d) : "r"(lo), "r"(hi)); return d;
}
__device__ __forceinline__ void upk(u64 v, unsigned& lo, unsigned& hi) {
    asm("mov.b64 {%0,%1},%2;" : "=r"(lo), "=r"(hi) : "l"(v));
}
__device__ __forceinline__ u64 bc(float f) {
    unsigned u = __float_as_uint(f); return pk2(u, u);
}
__device__ __forceinline__ u64 f2fma(u64 a, u64 b, u64 c) {
    u64 d; asm("fma.rn.f32x2 %0,%1,%2,%3;" : "=l"(d) : "l"(a), "l"(b), "l"(c)); return d;
}
__device__ __forceinline__ u64 f2mul(u64 a, u64 b) {
    u64 d; asm("mul.rn.f32x2 %0,%1,%2;" : "=l"(d) : "l"(a), "l"(b)); return d;
}
__device__ __forceinline__ u64 f2add(u64 a, u64 b) {
    u64 d; asm("add.rn.f32x2 %0,%1,%2;" : "=l"(d) : "l"(a), "l"(b)); return d;
}
__device__ __forceinline__ float ex2f(float x) {
    float y; asm("ex2.approx.f32 %0,%1;" : "=f"(y) : "f"(x)); return y;
}
__device__ __forceinline__ float lg2f(float x) {
    float y; asm("lg2.approx.f32 %0,%1;" : "=f"(y) : "f"(x)); return y;
}
__device__ __forceinline__ float rcpf(float x) {
    float y; asm("rcp.approx.f32 %0,%1;" : "=f"(y) : "f"(x)); return y;
}

// ---------------- precompute: fast-K formation, fp32 solve + fp64 refinement ----------------
__global__ void gp_pre(const float* __restrict__ z,
                       const float* __restrict__ h,
                       const float* __restrict__ raw_l) {
    int pid = blockIdx.x * blockDim.x + threadIdx.x;
    if (pid >= IDIM * OCH) return;
    int o = pid / IDIM, i = pid - o * IDIM;
    int oi = o * IDIM + i;

    // softplus via MUFU: sp = ln2 * lg2(1 + 2^(x*log2e))   (~1e-6 rel, chain ~5 ops)
    float x   = raw_l[oi];
    float tx  = ex2f(x * 1.4426950408889634f);
    float spf = 0.6931471805599453f * lg2f(1.0f + tx);
    float l2f = spf * spf;
    float cK  = -0.7213475204444817f * rcpf(l2f);   // -log2e/(2 l2)

    float zz[NP], hf[NP];
#pragma unroll
    for (int p = 0; p < NP; ++p) {
        zz[p] = z[oi * NP + p];
        hf[p] = h[oi * NP + p];
    }

    // K via ex2.approx (2ulp); fp64 copy for the refinement residual
    float  Kf[NP][NP];
    double Kd[NP][NP];
#pragma unroll
    for (int p = 0; p < NP; ++p)
#pragma unroll
        for (int q = 0; q < NP; ++q) {
            float dz = zz[p] - zz[q];
            float v = ex2f(dz * dz * cK) + (p == q ? 1e-4f : 0.0f);
            Kf[p][q] = v; Kd[p][q] = (double)v;
        }

    // fp32 Cholesky K = L L^T (rsqrt + 1 Newton)
    float L[NP][NP], rdiag[NP];
#pragma unroll
    for (int j = 0; j < NP; ++j) {
        float s = Kf[j][j];
#pragma unroll
        for (int k = 0; k < NP; ++k) if (k < j) s = fmaf(-L[j][k], L[j][k], s);
        float r = rsqrtf(s);
        r = r * fmaf(-0.5f * s * r, r, 1.5f);
        rdiag[j] = r;
        L[j][j] = s * r;
#pragma unroll
        for (int rr = 0; rr < NP; ++rr) if (rr > j) {
            float t = Kf[rr][j];
#pragma unroll
            for (int k = 0; k < NP; ++k) if (k < j) t = fmaf(-L[rr][k], L[j][k], t);
            L[rr][j] = t * r;
        }
    }
    // W = L^{-1} (lower): K^{-1} = W^T W
    float W[NP][NP];
#pragma unroll
    for (int j = 0; j < NP; ++j) {
        W[j][j] = rdiag[j];
#pragma unroll
        for (int rr = 0; rr < NP; ++rr) if (rr > j) {
            float t = 0.0f;
#pragma unroll
            for (int k = 0; k < NP; ++k) if (k >= j && k < rr) t = fmaf(L[rr][k], W[k][j], t);
            W[rr][j] = -t * rdiag[rr];
        }
    }

    // alpha0 = W^T (W h), then one fp64-residual refinement
    float t1[NP], a0[NP];
#pragma unroll
    for (int p = 0; p < NP; ++p) {
        float s = 0.0f;
#pragma unroll
        for (int q = 0; q < NP; ++q) if (q <= p) s = fmaf(W[p][q], hf[q], s);
        t1[p] = s;
    }
#pragma unroll
    for (int q = 0; q < NP; ++q) {
        float s = 0.0f;
#pragma unroll
        for (int p = 0; p < NP; ++p) if (p >= q) s = fmaf(W[p][q], t1[p], s);
        a0[q] = s;
    }
    float rf[NP];
#pragma unroll
    for (int p = 0; p < NP; ++p) {
        double s = (double)hf[p];
#pragma unroll
        for (int q = 0; q < NP; ++q) s = fma(-Kd[p][q], (double)a0[q], s);
        rf[p] = (float)s;
    }
    float t2[NP], al[NP];
#pragma unroll
    for (int p = 0; p < NP; ++p) {
        float s = 0.0f;
#pragma unroll
        for (int q = 0; q < NP; ++q) if (q <= p) s = fmaf(W[p][q], rf[q], s);
        t2[p] = s;
    }
#pragma unroll
    for (int q = 0; q < NP; ++q) {
        float s = a0[q];
#pragma unroll
        for (int p = 0; p < NP; ++p) if (p >= q) s = fmaf(W[p][q], t2[p], s);
        al[q] = s;
    }

    // record (float2-interleaved): l2, -z*5, (l*alpha)*5, (l*W)*15
    int og = o >> 1, lane = o & 1;
    float* rec = g_params + (i * 8 + og) * RECF + lane;
    rec[0] = l2f;
#pragma unroll
    for (int p = 0; p < NP; ++p) rec[(1 + p) * 2] = -zz[p];
#pragma unroll
    for (int p = 0; p < NP; ++p) rec[(6 + p) * 2] = spf * al[p];
#pragma unroll
    for (int p = 0; p < NP; ++p)
#pragma unroll
        for (int q = 0; q < NP; ++q) if (q <= p)
            rec[(11 + p * (p + 1) / 2 + q) * 2] = spf * W[p][q];
}

// ---------------- main: 6-way i-split, 4 rows/thread, EX2-based exps ----------------
__global__ __launch_bounds__(128) void gp_main(const float* __restrict__ xm,
                                               const float* __restrict__ xv) {
    __shared__ __align__(16) float2 ms_sm[IQ][ROWSB + 1];   // (mu, s2)
    __shared__ __align__(16) float  prm[IQ * 8 * RECS];

    const int tid   = threadIdx.x;
    const int row0  = blockIdx.x * ROWSB;
    const int split = blockIdx.y;
    const int i0    = split * IQ;

    // stage im2col(mu,s2) for this CTA's rows, this split's i-range
    for (int idx = tid; idx < IQ * ROWSB; idx += 128) {
        int il = idx >> 6, rlocal = idx & 63;
        int i = i0 + il;
        int c = i / 9, rem = i - c * 9;
        int kh = rem / 3, kw = rem - kh * 3;
        int r = row0 + rlocal;
        int n = r >> 10, oh = (r >> 5) & 31, ow = r & 31;
        int ih = oh + kh - 1, iw = ow + kw - 1;
        float m = 0.0f, v = 0.0f;
        if ((unsigned)ih < 32u && (unsigned)iw < 32u) {
            int g = ((n * 32 + ih) * 32 + iw) * 8 + c;
            m = xm[g]; v = xv[g];
        }
        ms_sm[il][rlocal] = make_float2(m, v);
    }
    // stage this split's param records: IQ x 8 x 13 uint4, contiguous in global
    {
        const uint4* src = reinterpret_cast<const uint4*>(g_params + i0 * 8 * RECF);
        for (int idx = tid; idx < IQ * 8 * 13; idx += 128) {
            int rrec = idx / 13, k4 = idx - rrec * 13;
            uint4 v4 = src[idx];
            *reinterpret_cast<uint4*>(&prm[rrec * RECS + 4 * k4]) = v4;
        }
    }
    __syncthreads();

    const int og = tid & 7;          // 8 o-pairs
    const int rp = tid >> 3;         // 16 row-quads -> rows rp*4 .. rp*4+3

    const u64 C_NHL2E = bc(-0.7213475204444817f);   // -0.5*log2(e)

    u64 macc[RPT] = {0ULL, 0ULL, 0ULL, 0ULL};
    u64 qacc[RPT] = {0ULL, 0ULL, 0ULL, 0ULL};

    for (int il = 0; il < IQ; ++il) {
        // record -> registers once, reused for RPT rows
        const uint4* Rq = reinterpret_cast<const uint4*>(&prm[(il * 8 + og) * RECS]);
        u64 P[RKU];
#pragma unroll
        for (int k4 = 0; k4 < 13; ++k4) {
            uint4 q = Rq[k4];
            P[2 * k4]     = pk2(q.x, q.y);
            P[2 * k4 + 1] = pk2(q.z, q.w);
        }
        const u64 l2 = P[0];

#pragma unroll
        for (int rr = 0; rr < RPT; ++rr) {
            const float2 msv = ms_sm[il][rp * RPT + rr];
            const u64 MU = bc(msv.x);
            const u64 S2 = bc(msv.y);

            // d = l2 + s2; r = 1/sqrt(d) via MUFU per half
            u64 d = f2add(l2, S2);
            unsigned dlo, dhi; upk(d, dlo, dhi);
            float rlo = rsqrtf(__uint_as_float(dlo));
            float rhi = rsqrtf(__uint_as_float(dhi));
            u64 r   = pk2(__float_as_uint(rlo), __float_as_uint(rhi));
            u64 rsq = f2mul(r, r);                   // 1/d
            const u64 ccp = f2mul(rsq, C_NHL2E);     // -log2e/(2d)

            // e_p = 2^( ccp*(mu-z_p)^2 ) via MUFU EX2 per half
            u64 e[NP];
#pragma unroll
            for (int p = 0; p < NP; ++p) {
                u64 t  = f2add(MU, P[1 + p]);        // P holds -z
                u64 t2 = f2mul(t, t);
                u64 y  = f2mul(t2, ccp);
                unsigned ylo, yhi; upk(y, ylo, yhi);
                float elo = ex2f(__uint_as_float(ylo));
                float ehi = ex2f(__uint_as_float(yhi));
                e[p] = pk2(__float_as_uint(elo), __float_as_uint(ehi));
            }

            // l*mean: e . alpha'  (alpha' = l*alpha at P[6..10])
            u64 me = f2mul(e[0], P[6]);
            me = f2fma(e[1], P[7],  me);
            me = f2fma(e[2], P[8],  me);
            me = f2fma(e[3], P[9],  me);
            me = f2fma(e[4], P[10], me);

            // l2*qKq = ||W' e||^2  (W' = l*W lower-tri at P[11..25])
            u64 v0 = f2mul(P[11], e[0]);
            u64 v1 = f2fma(P[13], e[1], f2mul(P[12], e[0]));
            u64 v2 = f2fma(P[16], e[2], f2fma(P[15], e[1], f2mul(P[14], e[0])));
            u64 v3 = f2fma(P[20], e[3], f2fma(P[19], e[2],
                     f2fma(P[18], e[1], f2mul(P[17], e[0]))));
            u64 v4 = f2fma(P[25], e[4], f2fma(P[24], e[3],
                     f2fma(P[23], e[2], f2fma(P[22], e[1], f2mul(P[21], e[0])))));
            u64 qk = f2mul(v0, v0);
            qk = f2fma(v1, v1, qk);
            qk = f2fma(v2, v2, qk);
            qk = f2fma(v3, v3, qk);
            qk = f2fma(v4, v4, qk);

            macc[rr] = f2fma(me, r,   macc[rr]);   // s*mean = r * (l*mean)
            qacc[rr] = f2fma(qk, rsq, qacc[rr]);   // (1/d) * (l2*qKq)
        }
    }

#pragma unroll
    for (int rr = 0; rr < RPT; ++rr) {
        const int r = row0 + rp * RPT + rr;
        unsigned mlo, mhi, qlo, qhi;
        upk(macc[rr], mlo, mhi); upk(qacc[rr], qlo, qhi);
        g_part[(split * NROWS + r) * 8 + og] =
            make_float4(__uint_as_float(mlo), __uint_as_float(mhi),
                        __uint_as_float(qlo), __uint_as_float(qhi));
    }
}

// ---------------- reduce: combine the 6 i-splits ----------------
__global__ __launch_bounds__(256) void gp_reduce(float* __restrict__ out) {
    int idx = blockIdx.x * 256 + threadIdx.x;       // over NROWS*8
    if (idx >= NROWS * 8) return;
    float4 a0 = g_part[idx];
    float4 a1 = g_part[NROWS * 8 + idx];
    float4 a2 = g_part[2 * NROWS * 8 + idx];
    float4 a3 = g_part[3 * NROWS * 8 + idx];
    float4 a4 = g_part[4 * NROWS * 8 + idx];
    float4 a5 = g_part[5 * NROWS * 8 + idx];
    float mx = ((a0.x + a1.x) + (a2.x + a3.x)) + (a4.x + a5.x);
    float my = ((a0.y + a1.y) + (a2.y + a3.y)) + (a4.y + a5.y);
    float qz = ((a0.z + a1.z) + (a2.z + a3.z)) + (a4.z + a5.z);
    float qw = ((a0.w + a1.w) + (a2.w + a3.w)) + (a4.w + a5.w);
    reinterpret_cast<float2*>(out)[idx] = make_float2(mx, my);
    reinterpret_cast<float2*>(out + NROWS * OCH)[idx] =
        make_float2(fmaxf(72.0f - qz, 1e-6f), fmaxf(72.0f - qw, 1e-6f));
}

extern "C" void kernel_launch(void* const* d_in, const int* in_sizes, int n_in,
                              void* d_out, int out_size) {
    const float* xm  = (const float*)d_in[0];  // x_mean [8,32,32,8]
    const float* xv  = (const float*)d_in[1];  // x_var
    const float* z   = (const float*)d_in[2];  // [16,72,5]
    const float* h   = (const float*)d_in[3];  // [16,72,5]
    const float* rlp = (const float*)d_in[4];  // [16,72]
    float* out = (float*)d_out;                // [m (131072) | v (131072)]

    gp_pre<<<36, 32>>>(z, h, rlp);
    gp_main<<<dim3(NROWS / ROWSB, ISPLIT), 128>>>(xm, xv);
    gp_reduce<<<NROWS * 8 / 256, 256>>>(out);
}